// round 10
// baseline (speedup 1.0000x reference)
#include <cuda_runtime.h>
#include <cuda_bf16.h>
#include <stdint.h>
#include <string.h>

// Problem constants
#define B_ 4
#define S_ 2048
#define D_ 1024
#define H_ 16
#define HS_ 64
#define MTOT (B_ * S_)   // 8192

// ---------------------------------------------------------------------------
// Pre-split bf16 hi/lo scratch (static device arrays — no allocation allowed)
// ---------------------------------------------------------------------------
__device__ __nv_bfloat16 g_xh[(size_t)MTOT * D_], g_xl[(size_t)MTOT * D_];
__device__ __nv_bfloat16 g_wqh[(size_t)D_ * D_], g_wql[(size_t)D_ * D_];
__device__ __nv_bfloat16 g_wkh[(size_t)D_ * D_], g_wkl[(size_t)D_ * D_];
__device__ __nv_bfloat16 g_wvh[(size_t)D_ * D_], g_wvl[(size_t)D_ * D_];
__device__ __nv_bfloat16 g_woh[(size_t)D_ * D_], g_wol[(size_t)D_ * D_];
// q,k,v: all [bh][s][hs] (q pre-scaled by 0.125 * log2(e))
__device__ __nv_bfloat16 g_qh[(size_t)64 * S_ * HS_], g_ql[(size_t)64 * S_ * HS_];
__device__ __nv_bfloat16 g_kh[(size_t)64 * S_ * HS_], g_kl[(size_t)64 * S_ * HS_];
__device__ __nv_bfloat16 g_vh[(size_t)64 * S_ * HS_], g_vl[(size_t)64 * S_ * HS_];
__device__ __nv_bfloat16 g_ctxh[(size_t)MTOT * D_], g_ctxl[(size_t)MTOT * D_];

// ---------------------------------------------------------------------------
// PTX helpers (arch-portable: sm_80+, valid on compute_103)
// ---------------------------------------------------------------------------
__device__ __forceinline__ uint32_t smem_u32(const void* p) {
    uint32_t a;
    asm("{ .reg .u64 t; cvta.to.shared.u64 t, %1; cvt.u32.u64 %0, t; }"
        : "=r"(a) : "l"(p));
    return a;
}

__device__ __forceinline__ float fast_exp2(float x) {
    float y;
    asm("ex2.approx.ftz.f32 %0, %1;" : "=f"(y) : "f"(x));
    return y;
}

#define CP_ASYNC16(dst, src) \
    asm volatile("cp.async.cg.shared.global [%0], [%1], 16;" \
        :: "r"(dst), "l"(src))
#define CP_COMMIT() asm volatile("cp.async.commit_group;" ::: "memory")
#define CP_WAIT(n)  asm volatile("cp.async.wait_group %0;" :: "n"(n) : "memory")

#define LDSM_X4(R, ADDR) \
    asm volatile("ldmatrix.sync.aligned.m8n8.x4.shared.b16 {%0,%1,%2,%3}, [%4];" \
        : "=r"((R)[0]), "=r"((R)[1]), "=r"((R)[2]), "=r"((R)[3]) : "r"(ADDR))

#define LDSM_X4_T(R, ADDR) \
    asm volatile("ldmatrix.sync.aligned.m8n8.x4.trans.shared.b16 {%0,%1,%2,%3}, [%4];" \
        : "=r"((R)[0]), "=r"((R)[1]), "=r"((R)[2]), "=r"((R)[3]) : "r"(ADDR))

#define MMA16816(C, A, B0, B1) \
    asm volatile("mma.sync.aligned.m16n8k16.row.col.f32.bf16.bf16.f32 " \
        "{%0,%1,%2,%3}, {%4,%5,%6,%7}, {%8,%9}, {%0,%1,%2,%3};" \
        : "+f"((C)[0]), "+f"((C)[1]), "+f"((C)[2]), "+f"((C)[3]) \
        : "r"((A)[0]), "r"((A)[1]), "r"((A)[2]), "r"((A)[3]), \
          "r"((B0)), "r"((B1)))

// Pack two floats into bf16x2 (hi) and residual bf16x2 (lo)
__device__ __forceinline__ void pack_hl(float a, float b,
                                        uint32_t& hi, uint32_t& lo) {
    __nv_bfloat162 h = __float22bfloat162_rn(make_float2(a, b));
    float2 f = __bfloat1622float2(h);
    __nv_bfloat162 l = __float22bfloat162_rn(make_float2(a - f.x, b - f.y));
    memcpy(&hi, &h, 4);
    memcpy(&lo, &l, 4);
}

// ---------------------------------------------------------------------------
// Combined split kernel: fp32 -> bf16 hi/lo for x + 4 weights, one launch.
// ---------------------------------------------------------------------------
__global__ __launch_bounds__(256, 4) void split_all_kernel(
    const float4* __restrict__ x,  const float4* __restrict__ Wq,
    const float4* __restrict__ Wk, const float4* __restrict__ Wv,
    const float4* __restrict__ Wo)
{
    const int bid = blockIdx.x;
    const float4* src;
    uint2 *dh, *dl;
    int base;
    if (bid < 8192)      { src = x;  dh = (uint2*)g_xh;  dl = (uint2*)g_xl;  base = bid; }
    else if (bid < 9216) { src = Wq; dh = (uint2*)g_wqh; dl = (uint2*)g_wql; base = bid - 8192; }
    else if (bid < 10240){ src = Wk; dh = (uint2*)g_wkh; dl = (uint2*)g_wkl; base = bid - 9216; }
    else if (bid < 11264){ src = Wv; dh = (uint2*)g_wvh; dl = (uint2*)g_wvl; base = bid - 10240; }
    else                 { src = Wo; dh = (uint2*)g_woh; dl = (uint2*)g_wol; base = bid - 11264; }
    const int i = base * 256 + threadIdx.x;
    float4 v = src[i];
    __nv_bfloat162 h01 = __float22bfloat162_rn(make_float2(v.x, v.y));
    __nv_bfloat162 h23 = __float22bfloat162_rn(make_float2(v.z, v.w));
    float2 f01 = __bfloat1622float2(h01);
    float2 f23 = __bfloat1622float2(h23);
    __nv_bfloat162 l01 = __float22bfloat162_rn(make_float2(v.x - f01.x, v.y - f01.y));
    __nv_bfloat162 l23 = __float22bfloat162_rn(make_float2(v.z - f23.x, v.w - f23.y));
    uint2 hv, lv;
    memcpy(&hv.x, &h01, 4); memcpy(&hv.y, &h23, 4);
    memcpy(&lv.x, &l01, 4); memcpy(&lv.y, &l23, 4);
    dh[i] = hv;
    dl[i] = lv;
}

// ---------------------------------------------------------------------------
// Split-bf16 GEMM: 256 threads, 8 warps (2x4), warp tile 64x64.
// CTA tile 128(M) x 256(N), BK=32, 3-stage cp.async, swizzled smem, 1 CTA/SM.
// 192 MMAs per warp between barriers (2x R8) -> barrier overhead halved
// relative to tensor-pipe work.
// Smem/stage: A 128x32 hi/lo = 16KB, B 256x32 hi/lo = 32KB -> 48KB; x3 = 144KB.
// ---------------------------------------------------------------------------
#define GTILE_A 16384u
#define GSTAGE 49152u
#define GEMM_DYN_SMEM (3 * 49152)

template<int MODE>
__global__ __launch_bounds__(256, 1) void gemm_kernel(
    const float* __restrict__ bo, float* __restrict__ outp)
{
    extern __shared__ char smem[];
    const int tid  = threadIdx.x;
    const int lane = tid & 31;
    const int wid  = tid >> 5;
    const int wm   = (wid & 1) * 64;      // 0 or 64
    const int wn   = (wid >> 1) * 64;     // 0, 64, 128, 192
    const int m0   = blockIdx.x * 128;
    const int n0   = blockIdx.y * 256;

    const __nv_bfloat16 *Ah, *Al, *Bh, *Bl;
    int nbase;
    if (MODE == 0) {
        Ah = g_xh; Al = g_xl;
        const int mat = n0 >> 10;        // 256-tile never straddles a matrix
        Bh = (mat == 0) ? g_wqh : ((mat == 1) ? g_wkh : g_wvh);
        Bl = (mat == 0) ? g_wql : ((mat == 1) ? g_wkl : g_wvl);
        nbase = n0 & 1023;
    } else {
        Ah = g_ctxh; Al = g_ctxl; Bh = g_woh; Bl = g_wol;
        nbase = n0;
    }

    // Loader: per thread row = tid>>3 (+32 per chunk), col = tid&7.
    // A: 4 chunks (128 rows), B: 8 chunks (256 rows). 16B each.
    const int lrow = tid >> 3, lcol = tid & 7;
    const char* aB = (const char*)(((lcol < 4) ? Ah : Al)
                     + (size_t)(m0 + lrow) * 1024 + (lcol & 3) * 8);
    const char* bB = (const char*)(((lcol < 4) ? Bh : Bl)
                     + (size_t)(nbase + lrow) * 1024 + (lcol & 3) * 8);
    // (lrow+32i)&7 == lrow&7, so swizzle term is i-invariant
    const uint32_t da = (uint32_t)(lrow * 128) + (uint32_t)((lcol ^ (lrow & 7)) << 4);
    const uint32_t db = GTILE_A + da;
    const uint32_t s0 = smem_u32(smem);

    // prologue: stages 0, 1
#pragma unroll
    for (int s = 0; s < 2; s++) {
        const uint32_t sb = s0 + (uint32_t)s * GSTAGE;
#pragma unroll
        for (int i = 0; i < 4; i++)
            CP_ASYNC16(sb + da + i * 4096, aB + s * 64 + (size_t)i * 65536);
#pragma unroll
        for (int i = 0; i < 8; i++)
            CP_ASYNC16(sb + db + i * 4096, bB + s * 64 + (size_t)i * 65536);
        CP_COMMIT();
    }

    float c[4][8][4];
#pragma unroll
    for (int i = 0; i < 4; i++)
#pragma unroll
        for (int j = 0; j < 8; j++)
#pragma unroll
            for (int q = 0; q < 4; q++) c[i][j][q] = 0.0f;

    const int l7 = lane & 7;
    const uint32_t arowoff = (uint32_t)((wm + (lane & 15)) * 128);
    const uint32_t browoff = (uint32_t)((wn + (lane & 7) + ((lane >> 4) & 1) * 8) * 128);

    int sb_idx = 0;
    for (int s = 0; s < 32; s++) {
        if (s == 31) { CP_WAIT(0); } else { CP_WAIT(1); }
        __syncthreads();
        if (s + 2 < 32) {
            const int nb = (sb_idx + 2 >= 3) ? sb_idx - 1 : sb_idx + 2;
            const uint32_t sb2 = s0 + (uint32_t)nb * GSTAGE;
#pragma unroll
            for (int i = 0; i < 4; i++)
                CP_ASYNC16(sb2 + da + i * 4096, aB + (s + 2) * 64 + (size_t)i * 65536);
#pragma unroll
            for (int i = 0; i < 8; i++)
                CP_ASYNC16(sb2 + db + i * 4096, bB + (s + 2) * 64 + (size_t)i * 65536);
            CP_COMMIT();
        }

        const uint32_t sb = s0 + (uint32_t)sb_idx * GSTAGE;
        const uint32_t sA = sb + arowoff;
        const uint32_t sB = sb + GTILE_A + browoff;
#pragma unroll
        for (int kk = 0; kk < 2; kk++) {
            const uint32_t offA = (uint32_t)(((kk * 2 + (lane >> 4)) ^ l7) << 4);
            const uint32_t offB = (uint32_t)(((kk * 2 + ((lane >> 3) & 1)) ^ l7) << 4);
            uint32_t bh4[4][4], bl4[4][4], ah[4][4], al[4][4];
#pragma unroll
            for (int g = 0; g < 4; g++) {
                LDSM_X4(bh4[g], sB + g * 2048 + offB);
                LDSM_X4(bl4[g], sB + g * 2048 + (offB ^ 64u));
            }
#pragma unroll
            for (int mi = 0; mi < 4; mi++) {
                LDSM_X4(ah[mi], sA + mi * 2048 + offA);
                LDSM_X4(al[mi], sA + mi * 2048 + (offA ^ 64u));
            }
#pragma unroll
            for (int mi = 0; mi < 4; mi++)
#pragma unroll
                for (int g = 0; g < 4; g++) {
                    MMA16816(c[mi][2 * g],     ah[mi], bh4[g][0], bh4[g][1]);
                    MMA16816(c[mi][2 * g + 1], ah[mi], bh4[g][2], bh4[g][3]);
                    MMA16816(c[mi][2 * g],     ah[mi], bl4[g][0], bl4[g][1]);
                    MMA16816(c[mi][2 * g + 1], ah[mi], bl4[g][2], bl4[g][3]);
                    MMA16816(c[mi][2 * g],     al[mi], bh4[g][0], bh4[g][1]);
                    MMA16816(c[mi][2 * g + 1], al[mi], bh4[g][2], bh4[g][3]);
                }
        }
        sb_idx = (sb_idx + 1 >= 3) ? 0 : sb_idx + 1;
    }

    // ---- epilogue (coalesced) ----
    const int mrow = lane >> 2;
    const int ncol = (lane & 3) * 2;
#pragma unroll
    for (int mi = 0; mi < 4; mi++)
#pragma unroll
        for (int nj = 0; nj < 8; nj++) {
            const int col = n0 + wn + nj * 8 + ncol;
#pragma unroll
            for (int half = 0; half < 2; half++) {
                const int m = m0 + wm + mi * 16 + mrow + half * 8;
                const float v0 = c[mi][nj][half * 2 + 0];
                const float v1 = c[mi][nj][half * 2 + 1];
                if (MODE == 0) {
                    const int mat = col >> 10;
                    const int loc = col & 1023;
                    const int h = loc >> 6, hs = loc & 63;
                    const int b = m >> 11, si = m & 2047;
                    const float sc = (mat == 0) ? 0.18033688f : 1.0f;
                    uint32_t hi, lo;
                    pack_hl(v0 * sc, v1 * sc, hi, lo);
                    __nv_bfloat16* dsth = (mat == 0) ? g_qh : ((mat == 1) ? g_kh : g_vh);
                    __nv_bfloat16* dstl = (mat == 0) ? g_ql : ((mat == 1) ? g_kl : g_vl);
                    const size_t p0 = (((size_t)(b * 16 + h)) * 2048 + si) * 64 + hs;
                    *(uint32_t*)&dsth[p0] = hi;
                    *(uint32_t*)&dstl[p0] = lo;
                } else {
                    *(float2*)&outp[(size_t)m * 1024 + col] =
                        make_float2(v0 + bo[col], v1 + bo[col + 1]);
                }
            }
        }
}

// ---------------------------------------------------------------------------
// Flash attention: swizzled smem (96KB), cp.async K/V dbl-buffer,
// V via ldmatrix.trans, softmax in exp2 domain. (unchanged)
// ---------------------------------------------------------------------------
#define FTILE 8192u
#define FSTAGE 32768u
#define FLASH_SMEM (32768 + 2 * 32768)   // 98304

__global__ __launch_bounds__(256, 2) void flash_mma_kernel()
{
    extern __shared__ char fsm[];
    const uint32_t s0 = smem_u32(fsm);
    const uint32_t oQl = 16384u, oKV = 32768u;

    const int tid = threadIdx.x, lane = tid & 31, wid = tid >> 5;
    const int qt = (int)gridDim.x - 1 - (int)blockIdx.x;   // heavy first
    const int bh = blockIdx.y;
    const int wm = wid * 16;
    const int l7 = lane & 7;

#pragma unroll
    for (int i = 0; i < 8; i++) {
        const int tile = i >> 2;
        const int cc   = (i & 3) * 256 + tid;
        const int row  = cc >> 3, col = cc & 7;
        const __nv_bfloat16* qsrc = ((tile == 0) ? g_qh : g_ql)
            + (size_t)bh * 131072 + (size_t)(qt * 128 + row) * 64 + col * 8;
        CP_ASYNC16(s0 + (uint32_t)tile * 16384u + (uint32_t)row * 128u
                       + (uint32_t)((col ^ (row & 7)) << 4), qsrc);
    }
    CP_COMMIT();

    const char* skv[8];
    uint32_t dkv[8];
#pragma unroll
    for (int i = 0; i < 8; i++) {
        const int tile = i >> 1;
        const int cc   = (i & 1) * 256 + tid;
        const int row  = cc >> 3, col = cc & 7;
        const __nv_bfloat16* bp =
            ((tile == 0) ? g_kh : (tile == 1) ? g_kl : (tile == 2) ? g_vh : g_vl)
            + (size_t)bh * 131072 + (size_t)row * 64 + col * 8;
        skv[i] = (const char*)bp;
        dkv[i] = oKV + (uint32_t)tile * FTILE + (uint32_t)row * 128u
               + (uint32_t)((col ^ (row & 7)) << 4);
    }
#pragma unroll
    for (int i = 0; i < 8; i++) CP_ASYNC16(s0 + dkv[i], skv[i]);
    CP_COMMIT();

    float o[8][4];
#pragma unroll
    for (int i = 0; i < 8; i++)
#pragma unroll
        for (int j = 0; j < 4; j++) o[i][j] = 0.0f;
    float mrow[2] = {-1e30f, -1e30f}, lrow[2] = {0.0f, 0.0f};

    const uint32_t aQ  = (uint32_t)((wm + (lane & 15)) * 128);
    const uint32_t bKV = (uint32_t)(((lane & 7) + ((lane >> 4) & 1) * 8) * 128);
    const int vrowb = (lane & 7) + 8 * ((lane >> 3) & 1);
    const int vsel  = (lane >> 4) & 1;

    const int nkt = 2 * qt + 2;
    for (int kt = 0; kt < nkt; kt++) {
        CP_WAIT(0);
        __syncthreads();
        if (kt + 1 < nkt) {
            const uint32_t st2 = (uint32_t)((kt + 1) & 1) * FSTAGE;
#pragma unroll
            for (int i = 0; i < 8; i++)
                CP_ASYNC16(s0 + st2 + dkv[i], skv[i] + (size_t)(kt + 1) * 8192);
            CP_COMMIT();
        }

        const uint32_t ss  = (uint32_t)(kt & 1) * FSTAGE;
        const uint32_t sKh = s0 + ss + oKV + bKV;
        const uint32_t sV  = s0 + ss + oKV + 2 * FTILE;

        float sc[8][4];
#pragma unroll
        for (int i = 0; i < 8; i++)
#pragma unroll
            for (int j = 0; j < 4; j++) sc[i][j] = 0.0f;
#pragma unroll
        for (int kk = 0; kk < 4; kk++) {
            const uint32_t offA = (uint32_t)(((kk * 2 + (lane >> 4)) ^ l7) << 4);
            const uint32_t offB = (uint32_t)(((kk * 2 + ((lane >> 3) & 1)) ^ l7) << 4);
            uint32_t ah[4], al[4];
            LDSM_X4(ah, s0 + aQ + offA);
            LDSM_X4(al, s0 + oQl + aQ + offA);
#pragma unroll
            for (int nt2 = 0; nt2 < 4; nt2++) {
                uint32_t bh4[4], bl4[4];
                LDSM_X4(bh4, sKh + nt2 * 2048 + offB);
                LDSM_X4(bl4, sKh + FTILE + nt2 * 2048 + offB);
                MMA16816(sc[2 * nt2],     ah, bh4[0], bh4[1]);
                MMA16816(sc[2 * nt2 + 1], ah, bh4[2], bh4[3]);
                MMA16816(sc[2 * nt2],     ah, bl4[0], bl4[1]);
                MMA16816(sc[2 * nt2 + 1], ah, bl4[2], bl4[3]);
                MMA16816(sc[2 * nt2],     al, bh4[0], bh4[1]);
                MMA16816(sc[2 * nt2 + 1], al, bh4[2], bh4[3]);
            }
        }

        if (kt >= 2 * qt) {
            const int baser = qt * 128 + wm + (lane >> 2);
            const int baseg = kt * 64 + ((lane & 3) << 1);
#pragma unroll
            for (int nt = 0; nt < 8; nt++)
#pragma unroll
                for (int j = 0; j < 4; j++) {
                    const int row = baser + ((j >> 1) << 3);
                    const int g   = baseg + nt * 8 + (j & 1);
                    if (g > row) sc[nt][j] = -1e30f;
                }
        }

#pragma unroll
        for (int hh = 0; hh < 2; hh++) {
            float rm = -1e30f;
#pragma unroll
            for (int nt = 0; nt < 8; nt++)
                rm = fmaxf(rm, fmaxf(sc[nt][2 * hh], sc[nt][2 * hh + 1]));
            rm = fmaxf(rm, __shfl_xor_sync(0xffffffffu, rm, 1));
            rm = fmaxf(rm, __shfl_xor_sync(0xffffffffu, rm, 2));
            const float mnew = fmaxf(mrow[hh], rm);
            const float corr = fast_exp2(mrow[hh] - mnew);
            mrow[hh] = mnew;
            float rs = 0.0f;
#pragma unroll
            for (int nt = 0; nt < 8; nt++) {
                sc[nt][2 * hh]     = fast_exp2(sc[nt][2 * hh] - mnew);
                sc[nt][2 * hh + 1] = fast_exp2(sc[nt][2 * hh + 1] - mnew);
                rs += sc[nt][2 * hh] + sc[nt][2 * hh + 1];
            }
            rs += __shfl_xor_sync(0xffffffffu, rs, 1);
            rs += __shfl_xor_sync(0xffffffffu, rs, 2);
            lrow[hh] = lrow[hh] * corr + rs;
#pragma unroll
            for (int nt = 0; nt < 8; nt++) {
                o[nt][2 * hh]     *= corr;
                o[nt][2 * hh + 1] *= corr;
            }
        }

#pragma unroll
        for (int t = 0; t < 4; t++) {
            const int vrow = t * 16 + vrowb;
            uint32_t ap[4], alp[4];
            pack_hl(sc[2 * t][0],     sc[2 * t][1],     ap[0], alp[0]);
            pack_hl(sc[2 * t][2],     sc[2 * t][3],     ap[1], alp[1]);
            pack_hl(sc[2 * t + 1][0], sc[2 * t + 1][1], ap[2], alp[2]);
            pack_hl(sc[2 * t + 1][2], sc[2 * t + 1][3], ap[3], alp[3]);
#pragma unroll
            for (int nt2 = 0; nt2 < 4; nt2++) {
                const int col16 = nt2 * 2 + vsel;
                const uint32_t vaddr = (uint32_t)(vrow * 128)
                                     + (uint32_t)((col16 ^ (vrow & 7)) << 4);
                uint32_t bh4[4], bl4[4];
                LDSM_X4_T(bh4, sV + vaddr);
                LDSM_X4_T(bl4, sV + FTILE + vaddr);
                MMA16816(o[2 * nt2],     ap,  bh4[0], bh4[1]);
                MMA16816(o[2 * nt2 + 1], ap,  bh4[2], bh4[3]);
                MMA16816(o[2 * nt2],     ap,  bl4[0], bl4[1]);
                MMA16816(o[2 * nt2 + 1], ap,  bl4[2], bl4[3]);
                MMA16816(o[2 * nt2],     alp, bh4[0], bh4[1]);
                MMA16816(o[2 * nt2 + 1], alp, bh4[2], bh4[3]);
            }
        }
    }

    const float inv0 = 1.0f / lrow[0];
    const float inv1 = 1.0f / lrow[1];
    const int b = bh >> 4, h = bh & 15;
    const int r0 = qt * 128 + wm + (lane >> 2);
    const int c0 = h * 64 + ((lane & 3) << 1);
#pragma unroll
    for (int nt = 0; nt < 8; nt++) {
        uint32_t hi, lo;
        pack_hl(o[nt][0] * inv0, o[nt][1] * inv0, hi, lo);
        const size_t p0 = (size_t)(b * 2048 + r0) * 1024 + c0 + nt * 8;
        *(uint32_t*)&g_ctxh[p0] = hi;
        *(uint32_t*)&g_ctxl[p0] = lo;
        pack_hl(o[nt][2] * inv1, o[nt][3] * inv1, hi, lo);
        const size_t p1 = (size_t)(b * 2048 + r0 + 8) * 1024 + c0 + nt * 8;
        *(uint32_t*)&g_ctxh[p1] = hi;
        *(uint32_t*)&g_ctxl[p1] = lo;
    }
}

// ---------------------------------------------------------------------------
// Launch.  Input order (metadata): x, Wk, Wq, Wv, Wo, bo
// ---------------------------------------------------------------------------
extern "C" void kernel_launch(void* const* d_in, const int* in_sizes, int n_in,
                              void* d_out, int out_size)
{
    const float* x  = (const float*)d_in[0];
    const float* Wk = (const float*)d_in[1];
    const float* Wq = (const float*)d_in[2];
    const float* Wv = (const float*)d_in[3];
    const float* Wo = (const float*)d_in[4];
    const float* bo = (const float*)d_in[5];
    float* out = (float*)d_out;

    static bool attr_done = false;
    if (!attr_done) {
        cudaFuncSetAttribute(gemm_kernel<0>,
                             cudaFuncAttributeMaxDynamicSharedMemorySize, GEMM_DYN_SMEM);
        cudaFuncSetAttribute(gemm_kernel<1>,
                             cudaFuncAttributeMaxDynamicSharedMemorySize, GEMM_DYN_SMEM);
        cudaFuncSetAttribute(flash_mma_kernel,
                             cudaFuncAttributeMaxDynamicSharedMemorySize, FLASH_SMEM);
        attr_done = true;
    }

    split_all_kernel<<<12288, 256>>>((const float4*)x, (const float4*)Wq,
                                     (const float4*)Wk, (const float4*)Wv,
                                     (const float4*)Wo);

    // QKV projection: M=8192, virtual N = [Wq | Wk | Wv] = 3072
    dim3 g1(MTOT / 128, 3072 / 256);     // 64 x 12
    gemm_kernel<0><<<g1, 256, GEMM_DYN_SMEM>>>(nullptr, nullptr);

    dim3 g2(S_ / 128, B_ * H_);          // 16 x 64
    flash_mma_kernel<<<g2, 256, FLASH_SMEM>>>();

    // Output projection: M=8192, N=1024 (+ bias)
    dim3 g3(MTOT / 128, 1024 / 256);     // 64 x 4
    gemm_kernel<1><<<g3, 256, GEMM_DYN_SMEM>>>(bo, out);
}

// round 12
// speedup vs baseline: 1.4239x; 1.4239x over previous
#include <cuda_runtime.h>
#include <cuda_fp16.h>
#include <stdint.h>
#include <string.h>

// Problem constants
#define B_ 4
#define S_ 2048
#define D_ 1024
#define H_ 16
#define HS_ 64
#define MTOT (B_ * S_)   // 8192

// ---------------------------------------------------------------------------
// Pre-split fp16 scratch (static device arrays — no allocation allowed)
// Weights: hi only (2-term asymmetric split). x/ctx: hi+lo. q,k: hi+lo. v: hi.
// ---------------------------------------------------------------------------
__device__ __half g_xh[(size_t)MTOT * D_], g_xl[(size_t)MTOT * D_];
__device__ __half g_wqh[(size_t)D_ * D_];
__device__ __half g_wkh[(size_t)D_ * D_];
__device__ __half g_wvh[(size_t)D_ * D_];
__device__ __half g_woh[(size_t)D_ * D_];
// q,k: [bh][s][hs] hi+lo (q pre-scaled by 0.125*log2e); v: [bh][s][hs] hi only
__device__ __half g_qh[(size_t)64 * S_ * HS_], g_ql[(size_t)64 * S_ * HS_];
__device__ __half g_kh[(size_t)64 * S_ * HS_], g_kl[(size_t)64 * S_ * HS_];
__device__ __half g_vh[(size_t)64 * S_ * HS_];
__device__ __half g_ctxh[(size_t)MTOT * D_], g_ctxl[(size_t)MTOT * D_];

// ---------------------------------------------------------------------------
// PTX helpers (arch-portable: sm_80+, valid on compute_103)
// ---------------------------------------------------------------------------
__device__ __forceinline__ uint32_t smem_u32(const void* p) {
    uint32_t a;
    asm("{ .reg .u64 t; cvta.to.shared.u64 t, %1; cvt.u32.u64 %0, t; }"
        : "=r"(a) : "l"(p));
    return a;
}

__device__ __forceinline__ float fast_exp2(float x) {
    float y;
    asm("ex2.approx.ftz.f32 %0, %1;" : "=f"(y) : "f"(x));
    return y;
}

#define CP_ASYNC16(dst, src) \
    asm volatile("cp.async.cg.shared.global [%0], [%1], 16;" \
        :: "r"(dst), "l"(src))
#define CP_COMMIT() asm volatile("cp.async.commit_group;" ::: "memory")
#define CP_WAIT(n)  asm volatile("cp.async.wait_group %0;" :: "n"(n) : "memory")

#define LDSM_X4(R, ADDR) \
    asm volatile("ldmatrix.sync.aligned.m8n8.x4.shared.b16 {%0,%1,%2,%3}, [%4];" \
        : "=r"((R)[0]), "=r"((R)[1]), "=r"((R)[2]), "=r"((R)[3]) : "r"(ADDR))

#define LDSM_X4_T(R, ADDR) \
    asm volatile("ldmatrix.sync.aligned.m8n8.x4.trans.shared.b16 {%0,%1,%2,%3}, [%4];" \
        : "=r"((R)[0]), "=r"((R)[1]), "=r"((R)[2]), "=r"((R)[3]) : "r"(ADDR))

// fp16 inputs, fp32 accumulate
#define MMA16816(C, A, B0, B1) \
    asm volatile("mma.sync.aligned.m16n8k16.row.col.f32.f16.f16.f32 " \
        "{%0,%1,%2,%3}, {%4,%5,%6,%7}, {%8,%9}, {%0,%1,%2,%3};" \
        : "+f"((C)[0]), "+f"((C)[1]), "+f"((C)[2]), "+f"((C)[3]) \
        : "r"((A)[0]), "r"((A)[1]), "r"((A)[2]), "r"((A)[3]), \
          "r"((B0)), "r"((B1)))

// Pack two floats into fp16x2 (hi) and residual fp16x2 (lo)
__device__ __forceinline__ void pack_hl(float a, float b,
                                        uint32_t& hi, uint32_t& lo) {
    __half2 h = __floats2half2_rn(a, b);
    float2 f = __half22float2(h);
    __half2 l = __floats2half2_rn(a - f.x, b - f.y);
    memcpy(&hi, &h, 4);
    memcpy(&lo, &l, 4);
}

// Mask / init constant: dominates all real scores, fits fp16 range, exp2 -> 0.
#define NEG_BIG (-30000.0f)

// ---------------------------------------------------------------------------
// Combined split kernel: x -> fp16 hi+lo; weights -> fp16 hi only.
// ---------------------------------------------------------------------------
__global__ __launch_bounds__(256, 4) void split_all_kernel(
    const float4* __restrict__ x,  const float4* __restrict__ Wq,
    const float4* __restrict__ Wk, const float4* __restrict__ Wv,
    const float4* __restrict__ Wo)
{
    const int bid = blockIdx.x;
    const float4* src;
    uint2 *dh, *dl;
    int base;
    if (bid < 8192)      { src = x;  dh = (uint2*)g_xh;  dl = (uint2*)g_xl; base = bid; }
    else if (bid < 9216) { src = Wq; dh = (uint2*)g_wqh; dl = nullptr; base = bid - 8192; }
    else if (bid < 10240){ src = Wk; dh = (uint2*)g_wkh; dl = nullptr; base = bid - 9216; }
    else if (bid < 11264){ src = Wv; dh = (uint2*)g_wvh; dl = nullptr; base = bid - 10240; }
    else                 { src = Wo; dh = (uint2*)g_woh; dl = nullptr; base = bid - 11264; }
    const int i = base * 256 + threadIdx.x;
    float4 v = src[i];
    __half2 h01 = __floats2half2_rn(v.x, v.y);
    __half2 h23 = __floats2half2_rn(v.z, v.w);
    uint2 hv;
    memcpy(&hv.x, &h01, 4); memcpy(&hv.y, &h23, 4);
    dh[i] = hv;
    if (dl) {
        float2 f01 = __half22float2(h01);
        float2 f23 = __half22float2(h23);
        __half2 l01 = __floats2half2_rn(v.x - f01.x, v.y - f01.y);
        __half2 l23 = __floats2half2_rn(v.z - f23.x, v.w - f23.y);
        uint2 lv;
        memcpy(&lv.x, &l01, 4); memcpy(&lv.y, &l23, 4);
        dl[i] = lv;
    }
}

// ---------------------------------------------------------------------------
// 2-term fp16 GEMM: C = (Ah + Al) . Bh   (A full precision, B hi only).
// 128 threads, 4 warps (2x2), warp tile 64x64, CTA 128x128, BK=32,
// 3-stage cp.async, swizzled smem, 2 CTAs/SM. (R9-proven shape + strides.)
// Loader: lrow = tid>>3 (0..15), 8 chunks of 16 rows:
//   smem stride 2048 B (16 rows x 128B), gmem stride 32768 B (16 rows x 2048B).
// ---------------------------------------------------------------------------
#define GTILE 16384u
#define GSTAGE 32768u
#define GEMM_DYN_SMEM (3 * 32768)

template<int MODE>
__global__ __launch_bounds__(128, 2) void gemm_kernel(
    const float* __restrict__ bo, float* __restrict__ outp)
{
    extern __shared__ char smem[];
    const int tid  = threadIdx.x;
    const int lane = tid & 31;
    const int wid  = tid >> 5;
    const int wm   = (wid & 1) * 64;
    const int wn   = (wid >> 1) * 64;
    const int m0   = blockIdx.x * 128;
    const int n0   = blockIdx.y * 128;

    const __half *Ah, *Al, *Bh;
    int nbase;
    if (MODE == 0) {
        Ah = g_xh; Al = g_xl;
        const int mat = n0 >> 10;
        Bh = (mat == 0) ? g_wqh : ((mat == 1) ? g_wkh : g_wvh);
        nbase = n0 & 1023;
    } else {
        Ah = g_ctxh; Al = g_ctxl; Bh = g_woh;
        nbase = n0;
    }

    // Loader: row = tid>>3 (+16 per chunk), col = tid&7.
    // A: col<4 -> Ah, col>=4 -> Al (k seg = col&3). B: only col<4 (hi).
    const int lrow = tid >> 3, lcol = tid & 7;
    const char* aB = (const char*)(((lcol < 4) ? Ah : Al)
                     + (size_t)(m0 + lrow) * 1024 + (lcol & 3) * 8);
    const char* bB = (const char*)(Bh
                     + (size_t)(nbase + lrow) * 1024 + (lcol & 3) * 8);
    const uint32_t da = (uint32_t)(lrow * 128) + (uint32_t)((lcol ^ (lrow & 7)) << 4);
    const uint32_t db = GTILE + da;
    const uint32_t s0 = smem_u32(smem);
    const bool doB = (lcol < 4);

    // prologue: stages 0, 1  (8 chunks x 16 rows each)
#pragma unroll
    for (int s = 0; s < 2; s++) {
        const uint32_t sb = s0 + (uint32_t)s * GSTAGE;
#pragma unroll
        for (int i = 0; i < 8; i++) {
            CP_ASYNC16(sb + da + i * 2048, aB + s * 64 + (size_t)i * 32768);
            if (doB)
                CP_ASYNC16(sb + db + i * 2048, bB + s * 64 + (size_t)i * 32768);
        }
        CP_COMMIT();
    }

    float c[4][8][4];
#pragma unroll
    for (int i = 0; i < 4; i++)
#pragma unroll
        for (int j = 0; j < 8; j++)
#pragma unroll
            for (int q = 0; q < 4; q++) c[i][j][q] = 0.0f;

    const int l7 = lane & 7;
    const uint32_t arowoff = (uint32_t)((wm + (lane & 15)) * 128);
    const uint32_t browoff = (uint32_t)((wn + (lane & 7) + ((lane >> 4) & 1) * 8) * 128);

    int sb_idx = 0;
    for (int s = 0; s < 32; s++) {
        if (s == 31) { CP_WAIT(0); } else { CP_WAIT(1); }
        __syncthreads();
        if (s + 2 < 32) {
            const int nb = (sb_idx + 2 >= 3) ? sb_idx - 1 : sb_idx + 2;
            const uint32_t sb2 = s0 + (uint32_t)nb * GSTAGE;
#pragma unroll
            for (int i = 0; i < 8; i++) {
                CP_ASYNC16(sb2 + da + i * 2048, aB + (s + 2) * 64 + (size_t)i * 32768);
                if (doB)
                    CP_ASYNC16(sb2 + db + i * 2048, bB + (s + 2) * 64 + (size_t)i * 32768);
            }
            CP_COMMIT();
        }

        const uint32_t sb = s0 + (uint32_t)sb_idx * GSTAGE;
        const uint32_t sA = sb + arowoff;
        const uint32_t sB = sb + GTILE + browoff;
#pragma unroll
        for (int kk = 0; kk < 2; kk++) {
            const uint32_t offA = (uint32_t)(((kk * 2 + (lane >> 4)) ^ l7) << 4);
            const uint32_t offB = (uint32_t)(((kk * 2 + ((lane >> 3) & 1)) ^ l7) << 4);
            uint32_t bh4[4][4];
#pragma unroll
            for (int g = 0; g < 4; g++)
                LDSM_X4(bh4[g], sB + g * 2048 + offB);
#pragma unroll
            for (int mi = 0; mi < 4; mi++) {
                uint32_t ah[4], al[4];
                LDSM_X4(ah, sA + mi * 2048 + offA);
                LDSM_X4(al, sA + mi * 2048 + (offA ^ 64u));
#pragma unroll
                for (int g = 0; g < 4; g++) {
                    MMA16816(c[mi][2 * g],     ah, bh4[g][0], bh4[g][1]);
                    MMA16816(c[mi][2 * g + 1], ah, bh4[g][2], bh4[g][3]);
                    MMA16816(c[mi][2 * g],     al, bh4[g][0], bh4[g][1]);
                    MMA16816(c[mi][2 * g + 1], al, bh4[g][2], bh4[g][3]);
                }
            }
        }
        sb_idx = (sb_idx + 1 >= 3) ? 0 : sb_idx + 1;
    }

    // ---- epilogue (coalesced) ----
    const int mrow = lane >> 2;
    const int ncol = (lane & 3) * 2;
#pragma unroll
    for (int mi = 0; mi < 4; mi++)
#pragma unroll
        for (int nj = 0; nj < 8; nj++) {
            const int col = n0 + wn + nj * 8 + ncol;
#pragma unroll
            for (int half = 0; half < 2; half++) {
                const int m = m0 + wm + mi * 16 + mrow + half * 8;
                const float v0 = c[mi][nj][half * 2 + 0];
                const float v1 = c[mi][nj][half * 2 + 1];
                if (MODE == 0) {
                    const int mat = col >> 10;
                    const int loc = col & 1023;
                    const int h = loc >> 6, hs = loc & 63;
                    const int b = m >> 11, si = m & 2047;
                    const size_t p0 = (((size_t)(b * 16 + h)) * 2048 + si) * 64 + hs;
                    if (mat == 2) {
                        __half2 hv = __floats2half2_rn(v0, v1);
                        uint32_t u; memcpy(&u, &hv, 4);
                        *(uint32_t*)&g_vh[p0] = u;
                    } else {
                        // q scaled by 0.125 * log2(e) for exp2-domain softmax
                        const float sc = (mat == 0) ? 0.18033688f : 1.0f;
                        uint32_t hi, lo;
                        pack_hl(v0 * sc, v1 * sc, hi, lo);
                        __half* dsth = (mat == 0) ? g_qh : g_kh;
                        __half* dstl = (mat == 0) ? g_ql : g_kl;
                        *(uint32_t*)&dsth[p0] = hi;
                        *(uint32_t*)&dstl[p0] = lo;
                    }
                } else {
                    *(float2*)&outp[(size_t)m * 1024 + col] =
                        make_float2(v0 + bo[col], v1 + bo[col + 1]);
                }
            }
        }
}

// ---------------------------------------------------------------------------
// Flash attention: QK 3-term fp16 (scores feed exp2 — precision critical),
// PV 2-term (P hi+lo x V hi). Swizzled smem, cp.async K/V double buffer,
// V via ldmatrix.trans, exp2-domain softmax, heavy-CTAs-first.
// Smem: Qh 16K | Ql 16K | 2 stages x (Kh 8K | Kl 8K | Vh 8K) = 80KB.
// ---------------------------------------------------------------------------
#define FTILE 8192u
#define FSTAGE 24576u
#define FLASH_SMEM (32768 + 2 * 24576)   // 81920

__global__ __launch_bounds__(256, 2) void flash_mma_kernel()
{
    extern __shared__ char fsm[];
    const uint32_t s0 = smem_u32(fsm);
    const uint32_t oQl = 16384u, oKV = 32768u;

    const int tid = threadIdx.x, lane = tid & 31, wid = tid >> 5;
    const int qt = (int)gridDim.x - 1 - (int)blockIdx.x;   // heavy first
    const int bh = blockIdx.y;
    const int wm = wid * 16;
    const int l7 = lane & 7;

    // ---- issue Q (hi/lo) via cp.async ----
#pragma unroll
    for (int i = 0; i < 8; i++) {
        const int tile = i >> 2;                 // 0 = Qh, 1 = Ql
        const int cc   = (i & 3) * 256 + tid;
        const int row  = cc >> 3, col = cc & 7;
        const __half* qsrc = ((tile == 0) ? g_qh : g_ql)
            + (size_t)bh * 131072 + (size_t)(qt * 128 + row) * 64 + col * 8;
        CP_ASYNC16(s0 + (uint32_t)tile * 16384u + (uint32_t)row * 128u
                       + (uint32_t)((col ^ (row & 7)) << 4), qsrc);
    }
    CP_COMMIT();

    // ---- KV loader: 3 tiles (Kh, Kl, Vh), each [64 keys][64 hs] ----
    const char* skv[6];
    uint32_t dkv[6];
#pragma unroll
    for (int i = 0; i < 6; i++) {
        const int tile = i >> 1;                 // 0=Kh, 1=Kl, 2=Vh
        const int cc   = (i & 1) * 256 + tid;
        const int row  = cc >> 3, col = cc & 7;
        const __half* bp =
            ((tile == 0) ? g_kh : (tile == 1) ? g_kl : g_vh)
            + (size_t)bh * 131072 + (size_t)row * 64 + col * 8;
        skv[i] = (const char*)bp;
        dkv[i] = oKV + (uint32_t)tile * FTILE + (uint32_t)row * 128u
               + (uint32_t)((col ^ (row & 7)) << 4);
    }
#pragma unroll
    for (int i = 0; i < 6; i++) CP_ASYNC16(s0 + dkv[i], skv[i]);
    CP_COMMIT();

    float o[8][4];
#pragma unroll
    for (int i = 0; i < 8; i++)
#pragma unroll
        for (int j = 0; j < 4; j++) o[i][j] = 0.0f;
    float mrow[2] = {NEG_BIG, NEG_BIG}, lrow[2] = {0.0f, 0.0f};

    const uint32_t aQ  = (uint32_t)((wm + (lane & 15)) * 128);
    const uint32_t bKV = (uint32_t)(((lane & 7) + ((lane >> 4) & 1) * 8) * 128);
    const int vrowb = (lane & 7) + 8 * ((lane >> 3) & 1);
    const int vsel  = (lane >> 4) & 1;

    const int nkt = 2 * qt + 2;
    for (int kt = 0; kt < nkt; kt++) {
        CP_WAIT(0);
        __syncthreads();
        if (kt + 1 < nkt) {
            const uint32_t st2 = (uint32_t)((kt + 1) & 1) * FSTAGE;
#pragma unroll
            for (int i = 0; i < 6; i++)
                CP_ASYNC16(s0 + st2 + dkv[i], skv[i] + (size_t)(kt + 1) * 8192);
            CP_COMMIT();
        }

        const uint32_t ss  = (uint32_t)(kt & 1) * FSTAGE;
        const uint32_t sKh = s0 + ss + oKV + bKV;
        const uint32_t sV  = s0 + ss + oKV + 2 * FTILE;

        // ---- S_log2 = Q @ K^T (3-term fp16 split) ----
        float sc[8][4];
#pragma unroll
        for (int i = 0; i < 8; i++)
#pragma unroll
            for (int j = 0; j < 4; j++) sc[i][j] = 0.0f;
#pragma unroll
        for (int kk = 0; kk < 4; kk++) {
            const uint32_t offA = (uint32_t)(((kk * 2 + (lane >> 4)) ^ l7) << 4);
            const uint32_t offB = (uint32_t)(((kk * 2 + ((lane >> 3) & 1)) ^ l7) << 4);
            uint32_t ah[4], al[4];
            LDSM_X4(ah, s0 + aQ + offA);
            LDSM_X4(al, s0 + oQl + aQ + offA);
#pragma unroll
            for (int nt2 = 0; nt2 < 4; nt2++) {
                uint32_t bh4[4], bl4[4];
                LDSM_X4(bh4, sKh + nt2 * 2048 + offB);
                LDSM_X4(bl4, sKh + FTILE + nt2 * 2048 + offB);
                MMA16816(sc[2 * nt2],     ah, bh4[0], bh4[1]);
                MMA16816(sc[2 * nt2 + 1], ah, bh4[2], bh4[3]);
                MMA16816(sc[2 * nt2],     ah, bl4[0], bl4[1]);
                MMA16816(sc[2 * nt2 + 1], ah, bl4[2], bl4[3]);
                MMA16816(sc[2 * nt2],     al, bh4[0], bh4[1]);
                MMA16816(sc[2 * nt2 + 1], al, bh4[2], bh4[3]);
            }
        }

        // ---- causal mask ----
        if (kt >= 2 * qt) {
            const int baser = qt * 128 + wm + (lane >> 2);
            const int baseg = kt * 64 + ((lane & 3) << 1);
#pragma unroll
            for (int nt = 0; nt < 8; nt++)
#pragma unroll
                for (int j = 0; j < 4; j++) {
                    const int row = baser + ((j >> 1) << 3);
                    const int g   = baseg + nt * 8 + (j & 1);
                    if (g > row) sc[nt][j] = NEG_BIG;
                }
        }

        // ---- online softmax (exp2 domain) ----
#pragma unroll
        for (int hh = 0; hh < 2; hh++) {
            float rm = NEG_BIG;
#pragma unroll
            for (int nt = 0; nt < 8; nt++)
                rm = fmaxf(rm, fmaxf(sc[nt][2 * hh], sc[nt][2 * hh + 1]));
            rm = fmaxf(rm, __shfl_xor_sync(0xffffffffu, rm, 1));
            rm = fmaxf(rm, __shfl_xor_sync(0xffffffffu, rm, 2));
            const float mnew = fmaxf(mrow[hh], rm);
            const float corr = fast_exp2(mrow[hh] - mnew);
            mrow[hh] = mnew;
            float rs = 0.0f;
#pragma unroll
            for (int nt = 0; nt < 8; nt++) {
                sc[nt][2 * hh]     = fast_exp2(sc[nt][2 * hh] - mnew);
                sc[nt][2 * hh + 1] = fast_exp2(sc[nt][2 * hh + 1] - mnew);
                rs += sc[nt][2 * hh] + sc[nt][2 * hh + 1];
            }
            rs += __shfl_xor_sync(0xffffffffu, rs, 1);
            rs += __shfl_xor_sync(0xffffffffu, rs, 2);
            lrow[hh] = lrow[hh] * corr + rs;
#pragma unroll
            for (int nt = 0; nt < 8; nt++) {
                o[nt][2 * hh]     *= corr;
                o[nt][2 * hh + 1] *= corr;
            }
        }

        // ---- O += P @ V (2-term: P hi+lo x V hi; V via trans-ldmatrix) ----
#pragma unroll
        for (int t = 0; t < 4; t++) {
            const int vrow = t * 16 + vrowb;
            uint32_t ap[4], alp[4];
            pack_hl(sc[2 * t][0],     sc[2 * t][1],     ap[0], alp[0]);
            pack_hl(sc[2 * t][2],     sc[2 * t][3],     ap[1], alp[1]);
            pack_hl(sc[2 * t + 1][0], sc[2 * t + 1][1], ap[2], alp[2]);
            pack_hl(sc[2 * t + 1][2], sc[2 * t + 1][3], ap[3], alp[3]);
#pragma unroll
            for (int nt2 = 0; nt2 < 4; nt2++) {
                const int col16 = nt2 * 2 + vsel;
                const uint32_t vaddr = (uint32_t)(vrow * 128)
                                     + (uint32_t)((col16 ^ (vrow & 7)) << 4);
                uint32_t bh4[4];
                LDSM_X4_T(bh4, sV + vaddr);
                MMA16816(o[2 * nt2],     ap,  bh4[0], bh4[1]);
                MMA16816(o[2 * nt2 + 1], ap,  bh4[2], bh4[3]);
                MMA16816(o[2 * nt2],     alp, bh4[0], bh4[1]);
                MMA16816(o[2 * nt2 + 1], alp, bh4[2], bh4[3]);
            }
        }
    }

    // ---- epilogue: normalize, split to ctx hi/lo fp16 ----
    const float inv0 = 1.0f / lrow[0];
    const float inv1 = 1.0f / lrow[1];
    const int b = bh >> 4, h = bh & 15;
    const int r0 = qt * 128 + wm + (lane >> 2);
    const int c0 = h * 64 + ((lane & 3) << 1);
#pragma unroll
    for (int nt = 0; nt < 8; nt++) {
        uint32_t hi, lo;
        pack_hl(o[nt][0] * inv0, o[nt][1] * inv0, hi, lo);
        const size_t p0 = (size_t)(b * 2048 + r0) * 1024 + c0 + nt * 8;
        *(uint32_t*)&g_ctxh[p0] = hi;
        *(uint32_t*)&g_ctxl[p0] = lo;
        pack_hl(o[nt][2] * inv1, o[nt][3] * inv1, hi, lo);
        const size_t p1 = (size_t)(b * 2048 + r0 + 8) * 1024 + c0 + nt * 8;
        *(uint32_t*)&g_ctxh[p1] = hi;
        *(uint32_t*)&g_ctxl[p1] = lo;
    }
}

// ---------------------------------------------------------------------------
// Launch.  Input order (metadata): x, Wk, Wq, Wv, Wo, bo
// ---------------------------------------------------------------------------
extern "C" void kernel_launch(void* const* d_in, const int* in_sizes, int n_in,
                              void* d_out, int out_size)
{
    const float* x  = (const float*)d_in[0];
    const float* Wk = (const float*)d_in[1];
    const float* Wq = (const float*)d_in[2];
    const float* Wv = (const float*)d_in[3];
    const float* Wo = (const float*)d_in[4];
    const float* bo = (const float*)d_in[5];
    float* out = (float*)d_out;

    static bool attr_done = false;
    if (!attr_done) {
        cudaFuncSetAttribute(gemm_kernel<0>,
                             cudaFuncAttributeMaxDynamicSharedMemorySize, GEMM_DYN_SMEM);
        cudaFuncSetAttribute(gemm_kernel<1>,
                             cudaFuncAttributeMaxDynamicSharedMemorySize, GEMM_DYN_SMEM);
        cudaFuncSetAttribute(flash_mma_kernel,
                             cudaFuncAttributeMaxDynamicSharedMemorySize, FLASH_SMEM);
        attr_done = true;
    }

    split_all_kernel<<<12288, 256>>>((const float4*)x, (const float4*)Wq,
                                     (const float4*)Wk, (const float4*)Wv,
                                     (const float4*)Wo);

    // QKV projection: M=8192, virtual N = [Wq | Wk | Wv] = 3072
    dim3 g1(MTOT / 128, 3072 / 128);     // 64 x 24, 128-thread CTAs
    gemm_kernel<0><<<g1, 128, GEMM_DYN_SMEM>>>(nullptr, nullptr);

    dim3 g2(S_ / 128, B_ * H_);          // 16 x 64
    flash_mma_kernel<<<g2, 256, FLASH_SMEM>>>();

    // Output projection: M=8192, N=1024 (+ bias)
    dim3 g3(MTOT / 128, 1024 / 128);     // 64 x 8
    gemm_kernel<1><<<g3, 128, GEMM_DYN_SMEM>>>(bo, out);
}

// round 13
// speedup vs baseline: 1.6953x; 1.1906x over previous
#include <cuda_runtime.h>
#include <cuda_fp16.h>
#include <stdint.h>
#include <string.h>

// Problem constants
#define B_ 4
#define S_ 2048
#define D_ 1024
#define H_ 16
#define HS_ 64
#define MTOT (B_ * S_)   // 8192

// ---------------------------------------------------------------------------
// Pre-split fp16 scratch (static device arrays — no allocation allowed)
// Weights: hi only. x: hi+lo (feeds exp-sensitive scores). q,k: hi+lo.
// v: hi. ctx: hi only (out-proj 1-term).
// ---------------------------------------------------------------------------
__device__ __half g_xh[(size_t)MTOT * D_], g_xl[(size_t)MTOT * D_];
__device__ __half g_wqh[(size_t)D_ * D_];
__device__ __half g_wkh[(size_t)D_ * D_];
__device__ __half g_wvh[(size_t)D_ * D_];
__device__ __half g_woh[(size_t)D_ * D_];
// q,k: [bh][s][hs] hi+lo (q pre-scaled by 0.125*log2e); v: [bh][s][hs] hi only
__device__ __half g_qh[(size_t)64 * S_ * HS_], g_ql[(size_t)64 * S_ * HS_];
__device__ __half g_kh[(size_t)64 * S_ * HS_], g_kl[(size_t)64 * S_ * HS_];
__device__ __half g_vh[(size_t)64 * S_ * HS_];
__device__ __half g_ctxh[(size_t)MTOT * D_];

// ---------------------------------------------------------------------------
// PTX helpers (arch-portable: sm_80+, valid on compute_103)
// ---------------------------------------------------------------------------
__device__ __forceinline__ uint32_t smem_u32(const void* p) {
    uint32_t a;
    asm("{ .reg .u64 t; cvta.to.shared.u64 t, %1; cvt.u32.u64 %0, t; }"
        : "=r"(a) : "l"(p));
    return a;
}

__device__ __forceinline__ float fast_exp2(float x) {
    float y;
    asm("ex2.approx.ftz.f32 %0, %1;" : "=f"(y) : "f"(x));
    return y;
}

#define CP_ASYNC16(dst, src) \
    asm volatile("cp.async.cg.shared.global [%0], [%1], 16;" \
        :: "r"(dst), "l"(src))
#define CP_COMMIT() asm volatile("cp.async.commit_group;" ::: "memory")
#define CP_WAIT(n)  asm volatile("cp.async.wait_group %0;" :: "n"(n) : "memory")

#define LDSM_X4(R, ADDR) \
    asm volatile("ldmatrix.sync.aligned.m8n8.x4.shared.b16 {%0,%1,%2,%3}, [%4];" \
        : "=r"((R)[0]), "=r"((R)[1]), "=r"((R)[2]), "=r"((R)[3]) : "r"(ADDR))

#define LDSM_X4_T(R, ADDR) \
    asm volatile("ldmatrix.sync.aligned.m8n8.x4.trans.shared.b16 {%0,%1,%2,%3}, [%4];" \
        : "=r"((R)[0]), "=r"((R)[1]), "=r"((R)[2]), "=r"((R)[3]) : "r"(ADDR))

// fp16 inputs, fp32 accumulate
#define MMA16816(C, A, B0, B1) \
    asm volatile("mma.sync.aligned.m16n8k16.row.col.f32.f16.f16.f32 " \
        "{%0,%1,%2,%3}, {%4,%5,%6,%7}, {%8,%9}, {%0,%1,%2,%3};" \
        : "+f"((C)[0]), "+f"((C)[1]), "+f"((C)[2]), "+f"((C)[3]) \
        : "r"((A)[0]), "r"((A)[1]), "r"((A)[2]), "r"((A)[3]), \
          "r"((B0)), "r"((B1)))

// Pack two floats into fp16x2 (hi) and residual fp16x2 (lo)
__device__ __forceinline__ void pack_hl(float a, float b,
                                        uint32_t& hi, uint32_t& lo) {
    __half2 h = __floats2half2_rn(a, b);
    float2 f = __half22float2(h);
    __half2 l = __floats2half2_rn(a - f.x, b - f.y);
    memcpy(&hi, &h, 4);
    memcpy(&lo, &l, 4);
}

__device__ __forceinline__ uint32_t pack_h(float a, float b) {
    __half2 h = __floats2half2_rn(a, b);
    uint32_t u; memcpy(&u, &h, 4);
    return u;
}

// Mask / init constant: dominates all real scores, fits fp16 range, exp2 -> 0.
#define NEG_BIG (-30000.0f)

// ---------------------------------------------------------------------------
// Combined split kernel: x -> fp16 hi+lo; weights -> fp16 hi only.
// ---------------------------------------------------------------------------
__global__ __launch_bounds__(256, 4) void split_all_kernel(
    const float4* __restrict__ x,  const float4* __restrict__ Wq,
    const float4* __restrict__ Wk, const float4* __restrict__ Wv,
    const float4* __restrict__ Wo)
{
    const int bid = blockIdx.x;
    const float4* src;
    uint2 *dh, *dl;
    int base;
    if (bid < 8192)      { src = x;  dh = (uint2*)g_xh;  dl = (uint2*)g_xl; base = bid; }
    else if (bid < 9216) { src = Wq; dh = (uint2*)g_wqh; dl = nullptr; base = bid - 8192; }
    else if (bid < 10240){ src = Wk; dh = (uint2*)g_wkh; dl = nullptr; base = bid - 9216; }
    else if (bid < 11264){ src = Wv; dh = (uint2*)g_wvh; dl = nullptr; base = bid - 10240; }
    else                 { src = Wo; dh = (uint2*)g_woh; dl = nullptr; base = bid - 11264; }
    const int i = base * 256 + threadIdx.x;
    float4 v = src[i];
    __half2 h01 = __floats2half2_rn(v.x, v.y);
    __half2 h23 = __floats2half2_rn(v.z, v.w);
    uint2 hv;
    memcpy(&hv.x, &h01, 4); memcpy(&hv.y, &h23, 4);
    dh[i] = hv;
    if (dl) {
        float2 f01 = __half22float2(h01);
        float2 f23 = __half22float2(h23);
        __half2 l01 = __floats2half2_rn(v.x - f01.x, v.y - f01.y);
        __half2 l23 = __floats2half2_rn(v.z - f23.x, v.w - f23.y);
        uint2 lv;
        memcpy(&lv.x, &l01, 4); memcpy(&lv.y, &l23, 4);
        dl[i] = lv;
    }
}

// ---------------------------------------------------------------------------
// fp16 GEMM, ATERMS-term A x 1-term B.
// MODE 0 (ATERMS=2): C = (Ah + Al) . Bh ; A = x, B = Wq/Wk/Wv.
// MODE 1 (ATERMS=1): C = Ah . Bh       ; A = ctx hi, B = Wo.
// 128 threads, 4 warps (2x2), warp tile 64x64, CTA 128x128, BK=32,
// 3-stage cp.async, swizzled smem, 2 CTAs/SM.
// ---------------------------------------------------------------------------
#define GTILE 16384u
#define GSTAGE 32768u
#define GEMM_DYN_SMEM (3 * 32768)

template<int MODE>
__global__ __launch_bounds__(128, 2) void gemm_kernel(
    const float* __restrict__ bo, float* __restrict__ outp)
{
    constexpr int ATERMS = (MODE == 0) ? 2 : 1;
    extern __shared__ char smem[];
    const int tid  = threadIdx.x;
    const int lane = tid & 31;
    const int wid  = tid >> 5;
    const int wm   = (wid & 1) * 64;
    const int wn   = (wid >> 1) * 64;
    const int m0   = blockIdx.x * 128;
    const int n0   = blockIdx.y * 128;

    const __half *Ah, *Al, *Bh;
    int nbase;
    if (MODE == 0) {
        Ah = g_xh; Al = g_xl;
        const int mat = n0 >> 10;
        Bh = (mat == 0) ? g_wqh : ((mat == 1) ? g_wkh : g_wvh);
        nbase = n0 & 1023;
    } else {
        Ah = g_ctxh; Al = g_ctxh;   // Al unused (guarded); keep pointer valid
        Bh = g_woh;
        nbase = n0;
    }

    // Loader: row = tid>>3 (+16 per chunk), col = tid&7.
    // A: col<4 -> Ah, col>=4 -> Al (only when ATERMS==2). B: col<4 only.
    const int lrow = tid >> 3, lcol = tid & 7;
    const char* aB = (const char*)(((lcol < 4) ? Ah : Al)
                     + (size_t)(m0 + lrow) * 1024 + (lcol & 3) * 8);
    const char* bB = (const char*)(Bh
                     + (size_t)(nbase + lrow) * 1024 + (lcol & 3) * 8);
    const uint32_t da = (uint32_t)(lrow * 128) + (uint32_t)((lcol ^ (lrow & 7)) << 4);
    const uint32_t db = GTILE + da;
    const uint32_t s0 = smem_u32(smem);
    const bool doB = (lcol < 4);
    const bool doA = (ATERMS == 2) || (lcol < 4);

    // prologue: stages 0, 1  (8 chunks x 16 rows each)
#pragma unroll
    for (int s = 0; s < 2; s++) {
        const uint32_t sb = s0 + (uint32_t)s * GSTAGE;
#pragma unroll
        for (int i = 0; i < 8; i++) {
            if (doA)
                CP_ASYNC16(sb + da + i * 2048, aB + s * 64 + (size_t)i * 32768);
            if (doB)
                CP_ASYNC16(sb + db + i * 2048, bB + s * 64 + (size_t)i * 32768);
        }
        CP_COMMIT();
    }

    float c[4][8][4];
#pragma unroll
    for (int i = 0; i < 4; i++)
#pragma unroll
        for (int j = 0; j < 8; j++)
#pragma unroll
            for (int q = 0; q < 4; q++) c[i][j][q] = 0.0f;

    const int l7 = lane & 7;
    const uint32_t arowoff = (uint32_t)((wm + (lane & 15)) * 128);
    const uint32_t browoff = (uint32_t)((wn + (lane & 7) + ((lane >> 4) & 1) * 8) * 128);

    int sb_idx = 0;
    for (int s = 0; s < 32; s++) {
        if (s == 31) { CP_WAIT(0); } else { CP_WAIT(1); }
        __syncthreads();
        if (s + 2 < 32) {
            const int nb = (sb_idx + 2 >= 3) ? sb_idx - 1 : sb_idx + 2;
            const uint32_t sb2 = s0 + (uint32_t)nb * GSTAGE;
#pragma unroll
            for (int i = 0; i < 8; i++) {
                if (doA)
                    CP_ASYNC16(sb2 + da + i * 2048, aB + (s + 2) * 64 + (size_t)i * 32768);
                if (doB)
                    CP_ASYNC16(sb2 + db + i * 2048, bB + (s + 2) * 64 + (size_t)i * 32768);
            }
            CP_COMMIT();
        }

        const uint32_t sb = s0 + (uint32_t)sb_idx * GSTAGE;
        const uint32_t sA = sb + arowoff;
        const uint32_t sB = sb + GTILE + browoff;
#pragma unroll
        for (int kk = 0; kk < 2; kk++) {
            const uint32_t offA = (uint32_t)(((kk * 2 + (lane >> 4)) ^ l7) << 4);
            const uint32_t offB = (uint32_t)(((kk * 2 + ((lane >> 3) & 1)) ^ l7) << 4);
            uint32_t bh4[4][4];
#pragma unroll
            for (int g = 0; g < 4; g++)
                LDSM_X4(bh4[g], sB + g * 2048 + offB);
#pragma unroll
            for (int mi = 0; mi < 4; mi++) {
                uint32_t ah[4], al[4];
                LDSM_X4(ah, sA + mi * 2048 + offA);
                if (ATERMS == 2)
                    LDSM_X4(al, sA + mi * 2048 + (offA ^ 64u));
#pragma unroll
                for (int g = 0; g < 4; g++) {
                    MMA16816(c[mi][2 * g],     ah, bh4[g][0], bh4[g][1]);
                    MMA16816(c[mi][2 * g + 1], ah, bh4[g][2], bh4[g][3]);
                    if (ATERMS == 2) {
                        MMA16816(c[mi][2 * g],     al, bh4[g][0], bh4[g][1]);
                        MMA16816(c[mi][2 * g + 1], al, bh4[g][2], bh4[g][3]);
                    }
                }
            }
        }
        sb_idx = (sb_idx + 1 >= 3) ? 0 : sb_idx + 1;
    }

    // ---- epilogue (coalesced) ----
    const int mrow = lane >> 2;
    const int ncol = (lane & 3) * 2;
#pragma unroll
    for (int mi = 0; mi < 4; mi++)
#pragma unroll
        for (int nj = 0; nj < 8; nj++) {
            const int col = n0 + wn + nj * 8 + ncol;
#pragma unroll
            for (int half = 0; half < 2; half++) {
                const int m = m0 + wm + mi * 16 + mrow + half * 8;
                const float v0 = c[mi][nj][half * 2 + 0];
                const float v1 = c[mi][nj][half * 2 + 1];
                if (MODE == 0) {
                    const int mat = col >> 10;
                    const int loc = col & 1023;
                    const int h = loc >> 6, hs = loc & 63;
                    const int b = m >> 11, si = m & 2047;
                    const size_t p0 = (((size_t)(b * 16 + h)) * 2048 + si) * 64 + hs;
                    if (mat == 2) {
                        *(uint32_t*)&g_vh[p0] = pack_h(v0, v1);
                    } else {
                        // q scaled by 0.125 * log2(e) for exp2-domain softmax
                        const float sc = (mat == 0) ? 0.18033688f : 1.0f;
                        uint32_t hi, lo;
                        pack_hl(v0 * sc, v1 * sc, hi, lo);
                        __half* dsth = (mat == 0) ? g_qh : g_kh;
                        __half* dstl = (mat == 0) ? g_ql : g_kl;
                        *(uint32_t*)&dsth[p0] = hi;
                        *(uint32_t*)&dstl[p0] = lo;
                    }
                } else {
                    *(float2*)&outp[(size_t)m * 1024 + col] =
                        make_float2(v0 + bo[col], v1 + bo[col + 1]);
                }
            }
        }
}

// ---------------------------------------------------------------------------
// Flash attention: QK 3-term fp16 (scores feed exp2 — precision critical),
// PV 1-term (P hi x V hi). Swizzled smem, cp.async K/V double buffer,
// V via ldmatrix.trans, exp2-domain softmax, heavy-CTAs-first.
// Smem: Qh 16K | Ql 16K | 2 stages x (Kh 8K | Kl 8K | Vh 8K) = 80KB.
// ---------------------------------------------------------------------------
#define FTILE 8192u
#define FSTAGE 24576u
#define FLASH_SMEM (32768 + 2 * 24576)   // 81920

__global__ __launch_bounds__(256, 2) void flash_mma_kernel()
{
    extern __shared__ char fsm[];
    const uint32_t s0 = smem_u32(fsm);
    const uint32_t oQl = 16384u, oKV = 32768u;

    const int tid = threadIdx.x, lane = tid & 31, wid = tid >> 5;
    const int qt = (int)gridDim.x - 1 - (int)blockIdx.x;   // heavy first
    const int bh = blockIdx.y;
    const int wm = wid * 16;
    const int l7 = lane & 7;

    // ---- issue Q (hi/lo) via cp.async ----
#pragma unroll
    for (int i = 0; i < 8; i++) {
        const int tile = i >> 2;                 // 0 = Qh, 1 = Ql
        const int cc   = (i & 3) * 256 + tid;
        const int row  = cc >> 3, col = cc & 7;
        const __half* qsrc = ((tile == 0) ? g_qh : g_ql)
            + (size_t)bh * 131072 + (size_t)(qt * 128 + row) * 64 + col * 8;
        CP_ASYNC16(s0 + (uint32_t)tile * 16384u + (uint32_t)row * 128u
                       + (uint32_t)((col ^ (row & 7)) << 4), qsrc);
    }
    CP_COMMIT();

    // ---- KV loader: 3 tiles (Kh, Kl, Vh), each [64 keys][64 hs] ----
    const char* skv[6];
    uint32_t dkv[6];
#pragma unroll
    for (int i = 0; i < 6; i++) {
        const int tile = i >> 1;                 // 0=Kh, 1=Kl, 2=Vh
        const int cc   = (i & 1) * 256 + tid;
        const int row  = cc >> 3, col = cc & 7;
        const __half* bp =
            ((tile == 0) ? g_kh : (tile == 1) ? g_kl : g_vh)
            + (size_t)bh * 131072 + (size_t)row * 64 + col * 8;
        skv[i] = (const char*)bp;
        dkv[i] = oKV + (uint32_t)tile * FTILE + (uint32_t)row * 128u
               + (uint32_t)((col ^ (row & 7)) << 4);
    }
#pragma unroll
    for (int i = 0; i < 6; i++) CP_ASYNC16(s0 + dkv[i], skv[i]);
    CP_COMMIT();

    float o[8][4];
#pragma unroll
    for (int i = 0; i < 8; i++)
#pragma unroll
        for (int j = 0; j < 4; j++) o[i][j] = 0.0f;
    float mrow[2] = {NEG_BIG, NEG_BIG}, lrow[2] = {0.0f, 0.0f};

    const uint32_t aQ  = (uint32_t)((wm + (lane & 15)) * 128);
    const uint32_t bKV = (uint32_t)(((lane & 7) + ((lane >> 4) & 1) * 8) * 128);
    const int vrowb = (lane & 7) + 8 * ((lane >> 3) & 1);
    const int vsel  = (lane >> 4) & 1;

    const int nkt = 2 * qt + 2;
    for (int kt = 0; kt < nkt; kt++) {
        CP_WAIT(0);
        __syncthreads();
        if (kt + 1 < nkt) {
            const uint32_t st2 = (uint32_t)((kt + 1) & 1) * FSTAGE;
#pragma unroll
            for (int i = 0; i < 6; i++)
                CP_ASYNC16(s0 + st2 + dkv[i], skv[i] + (size_t)(kt + 1) * 8192);
            CP_COMMIT();
        }

        const uint32_t ss  = (uint32_t)(kt & 1) * FSTAGE;
        const uint32_t sKh = s0 + ss + oKV + bKV;
        const uint32_t sV  = s0 + ss + oKV + 2 * FTILE;

        // ---- S_log2 = Q @ K^T (3-term fp16 split) ----
        float sc[8][4];
#pragma unroll
        for (int i = 0; i < 8; i++)
#pragma unroll
            for (int j = 0; j < 4; j++) sc[i][j] = 0.0f;
#pragma unroll
        for (int kk = 0; kk < 4; kk++) {
            const uint32_t offA = (uint32_t)(((kk * 2 + (lane >> 4)) ^ l7) << 4);
            const uint32_t offB = (uint32_t)(((kk * 2 + ((lane >> 3) & 1)) ^ l7) << 4);
            uint32_t ah[4], al[4];
            LDSM_X4(ah, s0 + aQ + offA);
            LDSM_X4(al, s0 + oQl + aQ + offA);
#pragma unroll
            for (int nt2 = 0; nt2 < 4; nt2++) {
                uint32_t bh4[4], bl4[4];
                LDSM_X4(bh4, sKh + nt2 * 2048 + offB);
                LDSM_X4(bl4, sKh + FTILE + nt2 * 2048 + offB);
                MMA16816(sc[2 * nt2],     ah, bh4[0], bh4[1]);
                MMA16816(sc[2 * nt2 + 1], ah, bh4[2], bh4[3]);
                MMA16816(sc[2 * nt2],     ah, bl4[0], bl4[1]);
                MMA16816(sc[2 * nt2 + 1], ah, bl4[2], bl4[3]);
                MMA16816(sc[2 * nt2],     al, bh4[0], bh4[1]);
                MMA16816(sc[2 * nt2 + 1], al, bh4[2], bh4[3]);
            }
        }

        // ---- causal mask ----
        if (kt >= 2 * qt) {
            const int baser = qt * 128 + wm + (lane >> 2);
            const int baseg = kt * 64 + ((lane & 3) << 1);
#pragma unroll
            for (int nt = 0; nt < 8; nt++)
#pragma unroll
                for (int j = 0; j < 4; j++) {
                    const int row = baser + ((j >> 1) << 3);
                    const int g   = baseg + nt * 8 + (j & 1);
                    if (g > row) sc[nt][j] = NEG_BIG;
                }
        }

        // ---- online softmax (exp2 domain) ----
#pragma unroll
        for (int hh = 0; hh < 2; hh++) {
            float rm = NEG_BIG;
#pragma unroll
            for (int nt = 0; nt < 8; nt++)
                rm = fmaxf(rm, fmaxf(sc[nt][2 * hh], sc[nt][2 * hh + 1]));
            rm = fmaxf(rm, __shfl_xor_sync(0xffffffffu, rm, 1));
            rm = fmaxf(rm, __shfl_xor_sync(0xffffffffu, rm, 2));
            const float mnew = fmaxf(mrow[hh], rm);
            const float corr = fast_exp2(mrow[hh] - mnew);
            mrow[hh] = mnew;
            float rs = 0.0f;
#pragma unroll
            for (int nt = 0; nt < 8; nt++) {
                sc[nt][2 * hh]     = fast_exp2(sc[nt][2 * hh] - mnew);
                sc[nt][2 * hh + 1] = fast_exp2(sc[nt][2 * hh + 1] - mnew);
                rs += sc[nt][2 * hh] + sc[nt][2 * hh + 1];
            }
            rs += __shfl_xor_sync(0xffffffffu, rs, 1);
            rs += __shfl_xor_sync(0xffffffffu, rs, 2);
            lrow[hh] = lrow[hh] * corr + rs;
#pragma unroll
            for (int nt = 0; nt < 8; nt++) {
                o[nt][2 * hh]     *= corr;
                o[nt][2 * hh + 1] *= corr;
            }
        }

        // ---- O += P @ V (1-term: P hi x V hi; V via trans-ldmatrix) ----
#pragma unroll
        for (int t = 0; t < 4; t++) {
            const int vrow = t * 16 + vrowb;
            uint32_t ap[4];
            ap[0] = pack_h(sc[2 * t][0],     sc[2 * t][1]);
            ap[1] = pack_h(sc[2 * t][2],     sc[2 * t][3]);
            ap[2] = pack_h(sc[2 * t + 1][0], sc[2 * t + 1][1]);
            ap[3] = pack_h(sc[2 * t + 1][2], sc[2 * t + 1][3]);
#pragma unroll
            for (int nt2 = 0; nt2 < 4; nt2++) {
                const int col16 = nt2 * 2 + vsel;
                const uint32_t vaddr = (uint32_t)(vrow * 128)
                                     + (uint32_t)((col16 ^ (vrow & 7)) << 4);
                uint32_t bh4[4];
                LDSM_X4_T(bh4, sV + vaddr);
                MMA16816(o[2 * nt2],     ap, bh4[0], bh4[1]);
                MMA16816(o[2 * nt2 + 1], ap, bh4[2], bh4[3]);
            }
        }
    }

    // ---- epilogue: normalize, write ctx hi fp16 ----
    const float inv0 = 1.0f / lrow[0];
    const float inv1 = 1.0f / lrow[1];
    const int b = bh >> 4, h = bh & 15;
    const int r0 = qt * 128 + wm + (lane >> 2);
    const int c0 = h * 64 + ((lane & 3) << 1);
#pragma unroll
    for (int nt = 0; nt < 8; nt++) {
        const size_t p0 = (size_t)(b * 2048 + r0) * 1024 + c0 + nt * 8;
        *(uint32_t*)&g_ctxh[p0] = pack_h(o[nt][0] * inv0, o[nt][1] * inv0);
        const size_t p1 = (size_t)(b * 2048 + r0 + 8) * 1024 + c0 + nt * 8;
        *(uint32_t*)&g_ctxh[p1] = pack_h(o[nt][2] * inv1, o[nt][3] * inv1);
    }
}

// ---------------------------------------------------------------------------
// Launch.  Input order (metadata): x, Wk, Wq, Wv, Wo, bo
// ---------------------------------------------------------------------------
extern "C" void kernel_launch(void* const* d_in, const int* in_sizes, int n_in,
                              void* d_out, int out_size)
{
    const float* x  = (const float*)d_in[0];
    const float* Wk = (const float*)d_in[1];
    const float* Wq = (const float*)d_in[2];
    const float* Wv = (const float*)d_in[3];
    const float* Wo = (const float*)d_in[4];
    const float* bo = (const float*)d_in[5];
    float* out = (float*)d_out;

    static bool attr_done = false;
    if (!attr_done) {
        cudaFuncSetAttribute(gemm_kernel<0>,
                             cudaFuncAttributeMaxDynamicSharedMemorySize, GEMM_DYN_SMEM);
        cudaFuncSetAttribute(gemm_kernel<1>,
                             cudaFuncAttributeMaxDynamicSharedMemorySize, GEMM_DYN_SMEM);
        cudaFuncSetAttribute(flash_mma_kernel,
                             cudaFuncAttributeMaxDynamicSharedMemorySize, FLASH_SMEM);
        attr_done = true;
    }

    split_all_kernel<<<12288, 256>>>((const float4*)x, (const float4*)Wq,
                                     (const float4*)Wk, (const float4*)Wv,
                                     (const float4*)Wo);

    // QKV projection: M=8192, virtual N = [Wq | Wk | Wv] = 3072
    dim3 g1(MTOT / 128, 3072 / 128);     // 64 x 24, 128-thread CTAs
    gemm_kernel<0><<<g1, 128, GEMM_DYN_SMEM>>>(nullptr, nullptr);

    dim3 g2(S_ / 128, B_ * H_);          // 16 x 64
    flash_mma_kernel<<<g2, 256, FLASH_SMEM>>>();

    // Output projection: M=8192, N=1024 (+ bias)
    dim3 g3(MTOT / 128, 1024 / 128);     // 64 x 8
    gemm_kernel<1><<<g3, 128, GEMM_DYN_SMEM>>>(bo, out);
}

// round 14
// speedup vs baseline: 2.1870x; 1.2901x over previous
#include <cuda_runtime.h>
#include <cuda_fp16.h>
#include <stdint.h>
#include <string.h>

// Problem constants
#define B_ 4
#define S_ 2048
#define D_ 1024
#define H_ 16
#define HS_ 64
#define MTOT (B_ * S_)   // 8192

// ---------------------------------------------------------------------------
// fp16 scratch (static device arrays — no allocation allowed)
// x, weights: hi only (1-term GEMMs). q,k: hi+lo (flash QK stays 3-term).
// v: hi. ctx: hi only (out-proj 1-term).
// ---------------------------------------------------------------------------
__device__ __half g_xh[(size_t)MTOT * D_];
__device__ __half g_wqh[(size_t)D_ * D_];
__device__ __half g_wkh[(size_t)D_ * D_];
__device__ __half g_wvh[(size_t)D_ * D_];
__device__ __half g_woh[(size_t)D_ * D_];
// q,k: [bh][s][hs] hi+lo (q pre-scaled by 0.125*log2e); v: [bh][s][hs] hi only
__device__ __half g_qh[(size_t)64 * S_ * HS_], g_ql[(size_t)64 * S_ * HS_];
__device__ __half g_kh[(size_t)64 * S_ * HS_], g_kl[(size_t)64 * S_ * HS_];
__device__ __half g_vh[(size_t)64 * S_ * HS_];
__device__ __half g_ctxh[(size_t)MTOT * D_];

// ---------------------------------------------------------------------------
// PTX helpers (arch-portable: sm_80+, valid on compute_103)
// ---------------------------------------------------------------------------
__device__ __forceinline__ uint32_t smem_u32(const void* p) {
    uint32_t a;
    asm("{ .reg .u64 t; cvta.to.shared.u64 t, %1; cvt.u32.u64 %0, t; }"
        : "=r"(a) : "l"(p));
    return a;
}

__device__ __forceinline__ float fast_exp2(float x) {
    float y;
    asm("ex2.approx.ftz.f32 %0, %1;" : "=f"(y) : "f"(x));
    return y;
}

#define CP_ASYNC16(dst, src) \
    asm volatile("cp.async.cg.shared.global [%0], [%1], 16;" \
        :: "r"(dst), "l"(src))
#define CP_COMMIT() asm volatile("cp.async.commit_group;" ::: "memory")
#define CP_WAIT(n)  asm volatile("cp.async.wait_group %0;" :: "n"(n) : "memory")

#define LDSM_X4(R, ADDR) \
    asm volatile("ldmatrix.sync.aligned.m8n8.x4.shared.b16 {%0,%1,%2,%3}, [%4];" \
        : "=r"((R)[0]), "=r"((R)[1]), "=r"((R)[2]), "=r"((R)[3]) : "r"(ADDR))

#define LDSM_X4_T(R, ADDR) \
    asm volatile("ldmatrix.sync.aligned.m8n8.x4.trans.shared.b16 {%0,%1,%2,%3}, [%4];" \
        : "=r"((R)[0]), "=r"((R)[1]), "=r"((R)[2]), "=r"((R)[3]) : "r"(ADDR))

// fp16 inputs, fp32 accumulate
#define MMA16816(C, A, B0, B1) \
    asm volatile("mma.sync.aligned.m16n8k16.row.col.f32.f16.f16.f32 " \
        "{%0,%1,%2,%3}, {%4,%5,%6,%7}, {%8,%9}, {%0,%1,%2,%3};" \
        : "+f"((C)[0]), "+f"((C)[1]), "+f"((C)[2]), "+f"((C)[3]) \
        : "r"((A)[0]), "r"((A)[1]), "r"((A)[2]), "r"((A)[3]), \
          "r"((B0)), "r"((B1)))

// Pack two floats into fp16x2 (hi) and residual fp16x2 (lo)
__device__ __forceinline__ void pack_hl(float a, float b,
                                        uint32_t& hi, uint32_t& lo) {
    __half2 h = __floats2half2_rn(a, b);
    float2 f = __half22float2(h);
    __half2 l = __floats2half2_rn(a - f.x, b - f.y);
    memcpy(&hi, &h, 4);
    memcpy(&lo, &l, 4);
}

__device__ __forceinline__ uint32_t pack_h(float a, float b) {
    __half2 h = __floats2half2_rn(a, b);
    uint32_t u; memcpy(&u, &h, 4);
    return u;
}

// Mask / init constant: dominates all real scores, fits fp16 range, exp2 -> 0.
#define NEG_BIG (-30000.0f)

// ---------------------------------------------------------------------------
// Combined split kernel: fp32 -> fp16 hi (all tensors 1-term now).
// ---------------------------------------------------------------------------
__global__ __launch_bounds__(256, 4) void split_all_kernel(
    const float4* __restrict__ x,  const float4* __restrict__ Wq,
    const float4* __restrict__ Wk, const float4* __restrict__ Wv,
    const float4* __restrict__ Wo)
{
    const int bid = blockIdx.x;
    const float4* src;
    uint2* dh;
    int base;
    if (bid < 8192)      { src = x;  dh = (uint2*)g_xh;  base = bid; }
    else if (bid < 9216) { src = Wq; dh = (uint2*)g_wqh; base = bid - 8192; }
    else if (bid < 10240){ src = Wk; dh = (uint2*)g_wkh; base = bid - 9216; }
    else if (bid < 11264){ src = Wv; dh = (uint2*)g_wvh; base = bid - 10240; }
    else                 { src = Wo; dh = (uint2*)g_woh; base = bid - 11264; }
    const int i = base * 256 + threadIdx.x;
    float4 v = src[i];
    __half2 h01 = __floats2half2_rn(v.x, v.y);
    __half2 h23 = __floats2half2_rn(v.z, v.w);
    uint2 hv;
    memcpy(&hv.x, &h01, 4); memcpy(&hv.y, &h23, 4);
    dh[i] = hv;
}

// ---------------------------------------------------------------------------
// 1-term fp16 GEMM: C = Ah . Bh.
// MODE 0: A = x hi, B = Wq/Wk/Wv hi; epilogue -> q,k (hi+lo split), v (hi).
// MODE 1: A = ctx hi, B = Wo hi; epilogue fp32 out + bias.
// 128 threads, 4 warps (2x2), warp tile 64x64, CTA 128x128, BK=32,
// 3-stage cp.async, swizzled smem, 2 CTAs/SM.
// Smem per stage: A hi 8KB (+8KB hole), B hi 8KB (+8KB hole) = 32KB layout kept
// for swizzle simplicity.
// ---------------------------------------------------------------------------
#define GTILE 16384u
#define GSTAGE 32768u
#define GEMM_DYN_SMEM (3 * 32768)

template<int MODE>
__global__ __launch_bounds__(128, 2) void gemm_kernel(
    const float* __restrict__ bo, float* __restrict__ outp)
{
    extern __shared__ char smem[];
    const int tid  = threadIdx.x;
    const int lane = tid & 31;
    const int wid  = tid >> 5;
    const int wm   = (wid & 1) * 64;
    const int wn   = (wid >> 1) * 64;
    const int m0   = blockIdx.x * 128;
    const int n0   = blockIdx.y * 128;

    const __half *Ah, *Bh;
    int nbase;
    if (MODE == 0) {
        Ah = g_xh;
        const int mat = n0 >> 10;
        Bh = (mat == 0) ? g_wqh : ((mat == 1) ? g_wkh : g_wvh);
        nbase = n0 & 1023;
    } else {
        Ah = g_ctxh;
        Bh = g_woh;
        nbase = n0;
    }

    // Loader: row = tid>>3 (+16 per chunk), col = tid&7; only col<4 (hi) issue.
    const int lrow = tid >> 3, lcol = tid & 7;
    const char* aB = (const char*)(Ah
                     + (size_t)(m0 + lrow) * 1024 + (lcol & 3) * 8);
    const char* bB = (const char*)(Bh
                     + (size_t)(nbase + lrow) * 1024 + (lcol & 3) * 8);
    const uint32_t da = (uint32_t)(lrow * 128) + (uint32_t)((lcol ^ (lrow & 7)) << 4);
    const uint32_t db = GTILE + da;
    const uint32_t s0 = smem_u32(smem);
    const bool doL = (lcol < 4);

    // prologue: stages 0, 1  (8 chunks x 16 rows each)
#pragma unroll
    for (int s = 0; s < 2; s++) {
        const uint32_t sb = s0 + (uint32_t)s * GSTAGE;
        if (doL) {
#pragma unroll
            for (int i = 0; i < 8; i++) {
                CP_ASYNC16(sb + da + i * 2048, aB + s * 64 + (size_t)i * 32768);
                CP_ASYNC16(sb + db + i * 2048, bB + s * 64 + (size_t)i * 32768);
            }
        }
        CP_COMMIT();
    }

    float c[4][8][4];
#pragma unroll
    for (int i = 0; i < 4; i++)
#pragma unroll
        for (int j = 0; j < 8; j++)
#pragma unroll
            for (int q = 0; q < 4; q++) c[i][j][q] = 0.0f;

    const int l7 = lane & 7;
    const uint32_t arowoff = (uint32_t)((wm + (lane & 15)) * 128);
    const uint32_t browoff = (uint32_t)((wn + (lane & 7) + ((lane >> 4) & 1) * 8) * 128);

    int sb_idx = 0;
    for (int s = 0; s < 32; s++) {
        if (s == 31) { CP_WAIT(0); } else { CP_WAIT(1); }
        __syncthreads();
        if (s + 2 < 32) {
            const int nb = (sb_idx + 2 >= 3) ? sb_idx - 1 : sb_idx + 2;
            const uint32_t sb2 = s0 + (uint32_t)nb * GSTAGE;
            if (doL) {
#pragma unroll
                for (int i = 0; i < 8; i++) {
                    CP_ASYNC16(sb2 + da + i * 2048, aB + (s + 2) * 64 + (size_t)i * 32768);
                    CP_ASYNC16(sb2 + db + i * 2048, bB + (s + 2) * 64 + (size_t)i * 32768);
                }
            }
            CP_COMMIT();
        }

        const uint32_t sb = s0 + (uint32_t)sb_idx * GSTAGE;
        const uint32_t sA = sb + arowoff;
        const uint32_t sB = sb + GTILE + browoff;
#pragma unroll
        for (int kk = 0; kk < 2; kk++) {
            const uint32_t offA = (uint32_t)(((kk * 2 + (lane >> 4)) ^ l7) << 4);
            const uint32_t offB = (uint32_t)(((kk * 2 + ((lane >> 3) & 1)) ^ l7) << 4);
            uint32_t bh4[4][4];
#pragma unroll
            for (int g = 0; g < 4; g++)
                LDSM_X4(bh4[g], sB + g * 2048 + offB);
#pragma unroll
            for (int mi = 0; mi < 4; mi++) {
                uint32_t ah[4];
                LDSM_X4(ah, sA + mi * 2048 + offA);
#pragma unroll
                for (int g = 0; g < 4; g++) {
                    MMA16816(c[mi][2 * g],     ah, bh4[g][0], bh4[g][1]);
                    MMA16816(c[mi][2 * g + 1], ah, bh4[g][2], bh4[g][3]);
                }
            }
        }
        sb_idx = (sb_idx + 1 >= 3) ? 0 : sb_idx + 1;
    }

    // ---- epilogue (coalesced) ----
    const int mrow = lane >> 2;
    const int ncol = (lane & 3) * 2;
#pragma unroll
    for (int mi = 0; mi < 4; mi++)
#pragma unroll
        for (int nj = 0; nj < 8; nj++) {
            const int col = n0 + wn + nj * 8 + ncol;
#pragma unroll
            for (int half = 0; half < 2; half++) {
                const int m = m0 + wm + mi * 16 + mrow + half * 8;
                const float v0 = c[mi][nj][half * 2 + 0];
                const float v1 = c[mi][nj][half * 2 + 1];
                if (MODE == 0) {
                    const int mat = col >> 10;
                    const int loc = col & 1023;
                    const int h = loc >> 6, hs = loc & 63;
                    const int b = m >> 11, si = m & 2047;
                    const size_t p0 = (((size_t)(b * 16 + h)) * 2048 + si) * 64 + hs;
                    if (mat == 2) {
                        *(uint32_t*)&g_vh[p0] = pack_h(v0, v1);
                    } else {
                        // q scaled by 0.125 * log2(e) for exp2-domain softmax
                        const float sc = (mat == 0) ? 0.18033688f : 1.0f;
                        uint32_t hi, lo;
                        pack_hl(v0 * sc, v1 * sc, hi, lo);
                        __half* dsth = (mat == 0) ? g_qh : g_kh;
                        __half* dstl = (mat == 0) ? g_ql : g_kl;
                        *(uint32_t*)&dsth[p0] = hi;
                        *(uint32_t*)&dstl[p0] = lo;
                    }
                } else {
                    *(float2*)&outp[(size_t)m * 1024 + col] =
                        make_float2(v0 + bo[col], v1 + bo[col + 1]);
                }
            }
        }
}

// ---------------------------------------------------------------------------
// Flash attention: QK 3-term fp16 (scores feed exp2 — precision critical),
// PV 1-term (P hi x V hi). Swizzled smem, cp.async K/V double buffer,
// V via ldmatrix.trans, exp2-domain softmax, heavy-CTAs-first.
// Smem: Qh 16K | Ql 16K | 2 stages x (Kh 8K | Kl 8K | Vh 8K) = 80KB.
// ---------------------------------------------------------------------------
#define FTILE 8192u
#define FSTAGE 24576u
#define FLASH_SMEM (32768 + 2 * 24576)   // 81920

__global__ __launch_bounds__(256, 2) void flash_mma_kernel()
{
    extern __shared__ char fsm[];
    const uint32_t s0 = smem_u32(fsm);
    const uint32_t oQl = 16384u, oKV = 32768u;

    const int tid = threadIdx.x, lane = tid & 31, wid = tid >> 5;
    const int qt = (int)gridDim.x - 1 - (int)blockIdx.x;   // heavy first
    const int bh = blockIdx.y;
    const int wm = wid * 16;
    const int l7 = lane & 7;

    // ---- issue Q (hi/lo) via cp.async ----
#pragma unroll
    for (int i = 0; i < 8; i++) {
        const int tile = i >> 2;                 // 0 = Qh, 1 = Ql
        const int cc   = (i & 3) * 256 + tid;
        const int row  = cc >> 3, col = cc & 7;
        const __half* qsrc = ((tile == 0) ? g_qh : g_ql)
            + (size_t)bh * 131072 + (size_t)(qt * 128 + row) * 64 + col * 8;
        CP_ASYNC16(s0 + (uint32_t)tile * 16384u + (uint32_t)row * 128u
                       + (uint32_t)((col ^ (row & 7)) << 4), qsrc);
    }
    CP_COMMIT();

    // ---- KV loader: 3 tiles (Kh, Kl, Vh), each [64 keys][64 hs] ----
    const char* skv[6];
    uint32_t dkv[6];
#pragma unroll
    for (int i = 0; i < 6; i++) {
        const int tile = i >> 1;                 // 0=Kh, 1=Kl, 2=Vh
        const int cc   = (i & 1) * 256 + tid;
        const int row  = cc >> 3, col = cc & 7;
        const __half* bp =
            ((tile == 0) ? g_kh : (tile == 1) ? g_kl : g_vh)
            + (size_t)bh * 131072 + (size_t)row * 64 + col * 8;
        skv[i] = (const char*)bp;
        dkv[i] = oKV + (uint32_t)tile * FTILE + (uint32_t)row * 128u
               + (uint32_t)((col ^ (row & 7)) << 4);
    }
#pragma unroll
    for (int i = 0; i < 6; i++) CP_ASYNC16(s0 + dkv[i], skv[i]);
    CP_COMMIT();

    float o[8][4];
#pragma unroll
    for (int i = 0; i < 8; i++)
#pragma unroll
        for (int j = 0; j < 4; j++) o[i][j] = 0.0f;
    float mrow[2] = {NEG_BIG, NEG_BIG}, lrow[2] = {0.0f, 0.0f};

    const uint32_t aQ  = (uint32_t)((wm + (lane & 15)) * 128);
    const uint32_t bKV = (uint32_t)(((lane & 7) + ((lane >> 4) & 1) * 8) * 128);
    const int vrowb = (lane & 7) + 8 * ((lane >> 3) & 1);
    const int vsel  = (lane >> 4) & 1;

    const int nkt = 2 * qt + 2;
    for (int kt = 0; kt < nkt; kt++) {
        CP_WAIT(0);
        __syncthreads();
        if (kt + 1 < nkt) {
            const uint32_t st2 = (uint32_t)((kt + 1) & 1) * FSTAGE;
#pragma unroll
            for (int i = 0; i < 6; i++)
                CP_ASYNC16(s0 + st2 + dkv[i], skv[i] + (size_t)(kt + 1) * 8192);
            CP_COMMIT();
        }

        const uint32_t ss  = (uint32_t)(kt & 1) * FSTAGE;
        const uint32_t sKh = s0 + ss + oKV + bKV;
        const uint32_t sV  = s0 + ss + oKV + 2 * FTILE;

        // ---- S_log2 = Q @ K^T (3-term fp16 split) ----
        float sc[8][4];
#pragma unroll
        for (int i = 0; i < 8; i++)
#pragma unroll
            for (int j = 0; j < 4; j++) sc[i][j] = 0.0f;
#pragma unroll
        for (int kk = 0; kk < 4; kk++) {
            const uint32_t offA = (uint32_t)(((kk * 2 + (lane >> 4)) ^ l7) << 4);
            const uint32_t offB = (uint32_t)(((kk * 2 + ((lane >> 3) & 1)) ^ l7) << 4);
            uint32_t ah[4], al[4];
            LDSM_X4(ah, s0 + aQ + offA);
            LDSM_X4(al, s0 + oQl + aQ + offA);
#pragma unroll
            for (int nt2 = 0; nt2 < 4; nt2++) {
                uint32_t bh4[4], bl4[4];
                LDSM_X4(bh4, sKh + nt2 * 2048 + offB);
                LDSM_X4(bl4, sKh + FTILE + nt2 * 2048 + offB);
                MMA16816(sc[2 * nt2],     ah, bh4[0], bh4[1]);
                MMA16816(sc[2 * nt2 + 1], ah, bh4[2], bh4[3]);
                MMA16816(sc[2 * nt2],     ah, bl4[0], bl4[1]);
                MMA16816(sc[2 * nt2 + 1], ah, bl4[2], bl4[3]);
                MMA16816(sc[2 * nt2],     al, bh4[0], bh4[1]);
                MMA16816(sc[2 * nt2 + 1], al, bh4[2], bh4[3]);
            }
        }

        // ---- causal mask ----
        if (kt >= 2 * qt) {
            const int baser = qt * 128 + wm + (lane >> 2);
            const int baseg = kt * 64 + ((lane & 3) << 1);
#pragma unroll
            for (int nt = 0; nt < 8; nt++)
#pragma unroll
                for (int j = 0; j < 4; j++) {
                    const int row = baser + ((j >> 1) << 3);
                    const int g   = baseg + nt * 8 + (j & 1);
                    if (g > row) sc[nt][j] = NEG_BIG;
                }
        }

        // ---- online softmax (exp2 domain) ----
#pragma unroll
        for (int hh = 0; hh < 2; hh++) {
            float rm = NEG_BIG;
#pragma unroll
            for (int nt = 0; nt < 8; nt++)
                rm = fmaxf(rm, fmaxf(sc[nt][2 * hh], sc[nt][2 * hh + 1]));
            rm = fmaxf(rm, __shfl_xor_sync(0xffffffffu, rm, 1));
            rm = fmaxf(rm, __shfl_xor_sync(0xffffffffu, rm, 2));
            const float mnew = fmaxf(mrow[hh], rm);
            const float corr = fast_exp2(mrow[hh] - mnew);
            mrow[hh] = mnew;
            float rs = 0.0f;
#pragma unroll
            for (int nt = 0; nt < 8; nt++) {
                sc[nt][2 * hh]     = fast_exp2(sc[nt][2 * hh] - mnew);
                sc[nt][2 * hh + 1] = fast_exp2(sc[nt][2 * hh + 1] - mnew);
                rs += sc[nt][2 * hh] + sc[nt][2 * hh + 1];
            }
            rs += __shfl_xor_sync(0xffffffffu, rs, 1);
            rs += __shfl_xor_sync(0xffffffffu, rs, 2);
            lrow[hh] = lrow[hh] * corr + rs;
#pragma unroll
            for (int nt = 0; nt < 8; nt++) {
                o[nt][2 * hh]     *= corr;
                o[nt][2 * hh + 1] *= corr;
            }
        }

        // ---- O += P @ V (1-term: P hi x V hi; V via trans-ldmatrix) ----
#pragma unroll
        for (int t = 0; t < 4; t++) {
            const int vrow = t * 16 + vrowb;
            uint32_t ap[4];
            ap[0] = pack_h(sc[2 * t][0],     sc[2 * t][1]);
            ap[1] = pack_h(sc[2 * t][2],     sc[2 * t][3]);
            ap[2] = pack_h(sc[2 * t + 1][0], sc[2 * t + 1][1]);
            ap[3] = pack_h(sc[2 * t + 1][2], sc[2 * t + 1][3]);
#pragma unroll
            for (int nt2 = 0; nt2 < 4; nt2++) {
                const int col16 = nt2 * 2 + vsel;
                const uint32_t vaddr = (uint32_t)(vrow * 128)
                                     + (uint32_t)((col16 ^ (vrow & 7)) << 4);
                uint32_t bh4[4];
                LDSM_X4_T(bh4, sV + vaddr);
                MMA16816(o[2 * nt2],     ap, bh4[0], bh4[1]);
                MMA16816(o[2 * nt2 + 1], ap, bh4[2], bh4[3]);
            }
        }
    }

    // ---- epilogue: normalize, write ctx hi fp16 ----
    const float inv0 = 1.0f / lrow[0];
    const float inv1 = 1.0f / lrow[1];
    const int b = bh >> 4, h = bh & 15;
    const int r0 = qt * 128 + wm + (lane >> 2);
    const int c0 = h * 64 + ((lane & 3) << 1);
#pragma unroll
    for (int nt = 0; nt < 8; nt++) {
        const size_t p0 = (size_t)(b * 2048 + r0) * 1024 + c0 + nt * 8;
        *(uint32_t*)&g_ctxh[p0] = pack_h(o[nt][0] * inv0, o[nt][1] * inv0);
        const size_t p1 = (size_t)(b * 2048 + r0 + 8) * 1024 + c0 + nt * 8;
        *(uint32_t*)&g_ctxh[p1] = pack_h(o[nt][2] * inv1, o[nt][3] * inv1);
    }
}

// ---------------------------------------------------------------------------
// Launch.  Input order (metadata): x, Wk, Wq, Wv, Wo, bo
// ---------------------------------------------------------------------------
extern "C" void kernel_launch(void* const* d_in, const int* in_sizes, int n_in,
                              void* d_out, int out_size)
{
    const float* x  = (const float*)d_in[0];
    const float* Wk = (const float*)d_in[1];
    const float* Wq = (const float*)d_in[2];
    const float* Wv = (const float*)d_in[3];
    const float* Wo = (const float*)d_in[4];
    const float* bo = (const float*)d_in[5];
    float* out = (float*)d_out;

    static bool attr_done = false;
    if (!attr_done) {
        cudaFuncSetAttribute(gemm_kernel<0>,
                             cudaFuncAttributeMaxDynamicSharedMemorySize, GEMM_DYN_SMEM);
        cudaFuncSetAttribute(gemm_kernel<1>,
                             cudaFuncAttributeMaxDynamicSharedMemorySize, GEMM_DYN_SMEM);
        cudaFuncSetAttribute(flash_mma_kernel,
                             cudaFuncAttributeMaxDynamicSharedMemorySize, FLASH_SMEM);
        attr_done = true;
    }

    split_all_kernel<<<12288, 256>>>((const float4*)x, (const float4*)Wq,
                                     (const float4*)Wk, (const float4*)Wv,
                                     (const float4*)Wo);

    // QKV projection: M=8192, virtual N = [Wq | Wk | Wv] = 3072
    dim3 g1(MTOT / 128, 3072 / 128);     // 64 x 24, 128-thread CTAs
    gemm_kernel<0><<<g1, 128, GEMM_DYN_SMEM>>>(nullptr, nullptr);

    dim3 g2(S_ / 128, B_ * H_);          // 16 x 64
    flash_mma_kernel<<<g2, 256, FLASH_SMEM>>>();

    // Output projection: M=8192, N=1024 (+ bias)
    dim3 g3(MTOT / 128, 1024 / 128);     // 64 x 8
    gemm_kernel<1><<<g3, 128, GEMM_DYN_SMEM>>>(bo, out);
}

// round 15
// speedup vs baseline: 2.8198x; 1.2893x over previous
#include <cuda_runtime.h>
#include <cuda_fp16.h>
#include <stdint.h>
#include <string.h>

// Problem constants
#define B_ 4
#define S_ 2048
#define D_ 1024
#define H_ 16
#define HS_ 64
#define MTOT (B_ * S_)   // 8192

// ---------------------------------------------------------------------------
// fp16 scratch (static device arrays — no allocation allowed)
// Everything 1-term fp16: x, W*, q, k, v, ctx.
// ---------------------------------------------------------------------------
__device__ __half g_xh[(size_t)MTOT * D_];
__device__ __half g_wqh[(size_t)D_ * D_];
__device__ __half g_wkh[(size_t)D_ * D_];
__device__ __half g_wvh[(size_t)D_ * D_];
__device__ __half g_woh[(size_t)D_ * D_];
// q,k,v: [bh][s][hs] fp16 (q pre-scaled by 0.125*log2e)
__device__ __half g_qh[(size_t)64 * S_ * HS_];
__device__ __half g_kh[(size_t)64 * S_ * HS_];
__device__ __half g_vh[(size_t)64 * S_ * HS_];
__device__ __half g_ctxh[(size_t)MTOT * D_];

// ---------------------------------------------------------------------------
// PTX helpers (arch-portable: sm_80+, valid on compute_103)
// ---------------------------------------------------------------------------
__device__ __forceinline__ uint32_t smem_u32(const void* p) {
    uint32_t a;
    asm("{ .reg .u64 t; cvta.to.shared.u64 t, %1; cvt.u32.u64 %0, t; }"
        : "=r"(a) : "l"(p));
    return a;
}

__device__ __forceinline__ float fast_exp2(float x) {
    float y;
    asm("ex2.approx.ftz.f32 %0, %1;" : "=f"(y) : "f"(x));
    return y;
}

#define CP_ASYNC16(dst, src) \
    asm volatile("cp.async.cg.shared.global [%0], [%1], 16;" \
        :: "r"(dst), "l"(src))
#define CP_COMMIT() asm volatile("cp.async.commit_group;" ::: "memory")
#define CP_WAIT(n)  asm volatile("cp.async.wait_group %0;" :: "n"(n) : "memory")

#define LDSM_X4(R, ADDR) \
    asm volatile("ldmatrix.sync.aligned.m8n8.x4.shared.b16 {%0,%1,%2,%3}, [%4];" \
        : "=r"((R)[0]), "=r"((R)[1]), "=r"((R)[2]), "=r"((R)[3]) : "r"(ADDR))

#define LDSM_X4_T(R, ADDR) \
    asm volatile("ldmatrix.sync.aligned.m8n8.x4.trans.shared.b16 {%0,%1,%2,%3}, [%4];" \
        : "=r"((R)[0]), "=r"((R)[1]), "=r"((R)[2]), "=r"((R)[3]) : "r"(ADDR))

// fp16 inputs, fp32 accumulate
#define MMA16816(C, A, B0, B1) \
    asm volatile("mma.sync.aligned.m16n8k16.row.col.f32.f16.f16.f32 " \
        "{%0,%1,%2,%3}, {%4,%5,%6,%7}, {%8,%9}, {%0,%1,%2,%3};" \
        : "+f"((C)[0]), "+f"((C)[1]), "+f"((C)[2]), "+f"((C)[3]) \
        : "r"((A)[0]), "r"((A)[1]), "r"((A)[2]), "r"((A)[3]), \
          "r"((B0)), "r"((B1)))

__device__ __forceinline__ uint32_t pack_h(float a, float b) {
    __half2 h = __floats2half2_rn(a, b);
    uint32_t u; memcpy(&u, &h, 4);
    return u;
}

// Mask / init constant: dominates all real scores, fits fp16 range, exp2 -> 0.
#define NEG_BIG (-30000.0f)

// ---------------------------------------------------------------------------
// Combined split kernel: fp32 -> fp16 (all tensors 1-term).
// ---------------------------------------------------------------------------
__global__ __launch_bounds__(256, 4) void split_all_kernel(
    const float4* __restrict__ x,  const float4* __restrict__ Wq,
    const float4* __restrict__ Wk, const float4* __restrict__ Wv,
    const float4* __restrict__ Wo)
{
    const int bid = blockIdx.x;
    const float4* src;
    uint2* dh;
    int base;
    if (bid < 8192)      { src = x;  dh = (uint2*)g_xh;  base = bid; }
    else if (bid < 9216) { src = Wq; dh = (uint2*)g_wqh; base = bid - 8192; }
    else if (bid < 10240){ src = Wk; dh = (uint2*)g_wkh; base = bid - 9216; }
    else if (bid < 11264){ src = Wv; dh = (uint2*)g_wvh; base = bid - 10240; }
    else                 { src = Wo; dh = (uint2*)g_woh; base = bid - 11264; }
    const int i = base * 256 + threadIdx.x;
    float4 v = src[i];
    __half2 h01 = __floats2half2_rn(v.x, v.y);
    __half2 h23 = __floats2half2_rn(v.z, v.w);
    uint2 hv;
    memcpy(&hv.x, &h01, 4); memcpy(&hv.y, &h23, 4);
    dh[i] = hv;
}

// ---------------------------------------------------------------------------
// 1-term fp16 GEMM: C = Ah . Bh.
// MODE 0: A = x, B = Wq/Wk/Wv; epilogue -> q (scaled), k, v fp16.
// MODE 1: A = ctx, B = Wo; epilogue fp32 out + bias.
// 128 threads, 4 warps (2x2), warp tile 64x64, CTA 128x128, BK=32,
// 3-stage cp.async, swizzled smem, 2 CTAs/SM.
// ---------------------------------------------------------------------------
#define GTILE 16384u
#define GSTAGE 32768u
#define GEMM_DYN_SMEM (3 * 32768)

template<int MODE>
__global__ __launch_bounds__(128, 2) void gemm_kernel(
    const float* __restrict__ bo, float* __restrict__ outp)
{
    extern __shared__ char smem[];
    const int tid  = threadIdx.x;
    const int lane = tid & 31;
    const int wid  = tid >> 5;
    const int wm   = (wid & 1) * 64;
    const int wn   = (wid >> 1) * 64;
    const int m0   = blockIdx.x * 128;
    const int n0   = blockIdx.y * 128;

    const __half *Ah, *Bh;
    int nbase;
    if (MODE == 0) {
        Ah = g_xh;
        const int mat = n0 >> 10;
        Bh = (mat == 0) ? g_wqh : ((mat == 1) ? g_wkh : g_wvh);
        nbase = n0 & 1023;
    } else {
        Ah = g_ctxh;
        Bh = g_woh;
        nbase = n0;
    }

    const int lrow = tid >> 3, lcol = tid & 7;
    const char* aB = (const char*)(Ah
                     + (size_t)(m0 + lrow) * 1024 + (lcol & 3) * 8);
    const char* bB = (const char*)(Bh
                     + (size_t)(nbase + lrow) * 1024 + (lcol & 3) * 8);
    const uint32_t da = (uint32_t)(lrow * 128) + (uint32_t)((lcol ^ (lrow & 7)) << 4);
    const uint32_t db = GTILE + da;
    const uint32_t s0 = smem_u32(smem);
    const bool doL = (lcol < 4);

#pragma unroll
    for (int s = 0; s < 2; s++) {
        const uint32_t sb = s0 + (uint32_t)s * GSTAGE;
        if (doL) {
#pragma unroll
            for (int i = 0; i < 8; i++) {
                CP_ASYNC16(sb + da + i * 2048, aB + s * 64 + (size_t)i * 32768);
                CP_ASYNC16(sb + db + i * 2048, bB + s * 64 + (size_t)i * 32768);
            }
        }
        CP_COMMIT();
    }

    float c[4][8][4];
#pragma unroll
    for (int i = 0; i < 4; i++)
#pragma unroll
        for (int j = 0; j < 8; j++)
#pragma unroll
            for (int q = 0; q < 4; q++) c[i][j][q] = 0.0f;

    const int l7 = lane & 7;
    const uint32_t arowoff = (uint32_t)((wm + (lane & 15)) * 128);
    const uint32_t browoff = (uint32_t)((wn + (lane & 7) + ((lane >> 4) & 1) * 8) * 128);

    int sb_idx = 0;
    for (int s = 0; s < 32; s++) {
        if (s == 31) { CP_WAIT(0); } else { CP_WAIT(1); }
        __syncthreads();
        if (s + 2 < 32) {
            const int nb = (sb_idx + 2 >= 3) ? sb_idx - 1 : sb_idx + 2;
            const uint32_t sb2 = s0 + (uint32_t)nb * GSTAGE;
            if (doL) {
#pragma unroll
                for (int i = 0; i < 8; i++) {
                    CP_ASYNC16(sb2 + da + i * 2048, aB + (s + 2) * 64 + (size_t)i * 32768);
                    CP_ASYNC16(sb2 + db + i * 2048, bB + (s + 2) * 64 + (size_t)i * 32768);
                }
            }
            CP_COMMIT();
        }

        const uint32_t sb = s0 + (uint32_t)sb_idx * GSTAGE;
        const uint32_t sA = sb + arowoff;
        const uint32_t sB = sb + GTILE + browoff;
#pragma unroll
        for (int kk = 0; kk < 2; kk++) {
            const uint32_t offA = (uint32_t)(((kk * 2 + (lane >> 4)) ^ l7) << 4);
            const uint32_t offB = (uint32_t)(((kk * 2 + ((lane >> 3) & 1)) ^ l7) << 4);
            uint32_t bh4[4][4];
#pragma unroll
            for (int g = 0; g < 4; g++)
                LDSM_X4(bh4[g], sB + g * 2048 + offB);
#pragma unroll
            for (int mi = 0; mi < 4; mi++) {
                uint32_t ah[4];
                LDSM_X4(ah, sA + mi * 2048 + offA);
#pragma unroll
                for (int g = 0; g < 4; g++) {
                    MMA16816(c[mi][2 * g],     ah, bh4[g][0], bh4[g][1]);
                    MMA16816(c[mi][2 * g + 1], ah, bh4[g][2], bh4[g][3]);
                }
            }
        }
        sb_idx = (sb_idx + 1 >= 3) ? 0 : sb_idx + 1;
    }

    // ---- epilogue (coalesced) ----
    const int mrow = lane >> 2;
    const int ncol = (lane & 3) * 2;
#pragma unroll
    for (int mi = 0; mi < 4; mi++)
#pragma unroll
        for (int nj = 0; nj < 8; nj++) {
            const int col = n0 + wn + nj * 8 + ncol;
#pragma unroll
            for (int half = 0; half < 2; half++) {
                const int m = m0 + wm + mi * 16 + mrow + half * 8;
                const float v0 = c[mi][nj][half * 2 + 0];
                const float v1 = c[mi][nj][half * 2 + 1];
                if (MODE == 0) {
                    const int mat = col >> 10;
                    const int loc = col & 1023;
                    const int h = loc >> 6, hs = loc & 63;
                    const int b = m >> 11, si = m & 2047;
                    const size_t p0 = (((size_t)(b * 16 + h)) * 2048 + si) * 64 + hs;
                    // q scaled by 0.125 * log2(e) for exp2-domain softmax
                    const float sc = (mat == 0) ? 0.18033688f : 1.0f;
                    __half* dst = (mat == 0) ? g_qh : ((mat == 1) ? g_kh : g_vh);
                    *(uint32_t*)&dst[p0] = pack_h(v0 * sc, v1 * sc);
                } else {
                    *(float2*)&outp[(size_t)m * 1024 + col] =
                        make_float2(v0 + bo[col], v1 + bo[col + 1]);
                }
            }
        }
}

// ---------------------------------------------------------------------------
// Flash attention: QK 1-term fp16, PV 1-term fp16 (fp32 accum everywhere).
// Swizzled smem, cp.async K/V double buffer, V via ldmatrix.trans,
// exp2-domain softmax, heavy-CTAs-first.
// Smem: Q 16K | 2 stages x (K 8K | V 8K) = 48KB total.
// ---------------------------------------------------------------------------
#define FTILE 8192u
#define FSTAGE 16384u
#define FLASH_SMEM (16384 + 2 * 16384)   // 49152

__global__ __launch_bounds__(256, 2) void flash_mma_kernel()
{
    extern __shared__ char fsm[];
    const uint32_t s0 = smem_u32(fsm);
    const uint32_t oKV = 16384u;

    const int tid = threadIdx.x, lane = tid & 31, wid = tid >> 5;
    const int qt = (int)gridDim.x - 1 - (int)blockIdx.x;   // heavy first
    const int bh = blockIdx.y;
    const int wm = wid * 16;
    const int l7 = lane & 7;

    // ---- issue Q via cp.async (128 x 64 fp16 = 16KB = 1024 chunks) ----
#pragma unroll
    for (int i = 0; i < 4; i++) {
        const int cc  = i * 256 + tid;
        const int row = cc >> 3, col = cc & 7;
        const __half* qsrc = g_qh
            + (size_t)bh * 131072 + (size_t)(qt * 128 + row) * 64 + col * 8;
        CP_ASYNC16(s0 + (uint32_t)row * 128u
                       + (uint32_t)((col ^ (row & 7)) << 4), qsrc);
    }
    CP_COMMIT();

    // ---- KV loader: 2 tiles (K, V), each [64 keys][64 hs] = 512 chunks ----
    const char* skv[4];
    uint32_t dkv[4];
#pragma unroll
    for (int i = 0; i < 4; i++) {
        const int tile = i >> 1;                 // 0=K, 1=V
        const int cc   = (i & 1) * 256 + tid;
        const int row  = cc >> 3, col = cc & 7;
        const __half* bp = ((tile == 0) ? g_kh : g_vh)
            + (size_t)bh * 131072 + (size_t)row * 64 + col * 8;
        skv[i] = (const char*)bp;
        dkv[i] = oKV + (uint32_t)tile * FTILE + (uint32_t)row * 128u
               + (uint32_t)((col ^ (row & 7)) << 4);
    }
#pragma unroll
    for (int i = 0; i < 4; i++) CP_ASYNC16(s0 + dkv[i], skv[i]);
    CP_COMMIT();

    float o[8][4];
#pragma unroll
    for (int i = 0; i < 8; i++)
#pragma unroll
        for (int j = 0; j < 4; j++) o[i][j] = 0.0f;
    float mrow[2] = {NEG_BIG, NEG_BIG}, lrow[2] = {0.0f, 0.0f};

    const uint32_t aQ  = (uint32_t)((wm + (lane & 15)) * 128);
    const uint32_t bKV = (uint32_t)(((lane & 7) + ((lane >> 4) & 1) * 8) * 128);
    const int vrowb = (lane & 7) + 8 * ((lane >> 3) & 1);
    const int vsel  = (lane >> 4) & 1;

    const int nkt = 2 * qt + 2;
    for (int kt = 0; kt < nkt; kt++) {
        CP_WAIT(0);
        __syncthreads();
        if (kt + 1 < nkt) {
            const uint32_t st2 = (uint32_t)((kt + 1) & 1) * FSTAGE;
#pragma unroll
            for (int i = 0; i < 4; i++)
                CP_ASYNC16(s0 + st2 + dkv[i], skv[i] + (size_t)(kt + 1) * 8192);
            CP_COMMIT();
        }

        const uint32_t ss = (uint32_t)(kt & 1) * FSTAGE;
        const uint32_t sK = s0 + ss + oKV + bKV;
        const uint32_t sV = s0 + ss + oKV + FTILE;

        // ---- S_log2 = Q @ K^T (1-term fp16) ----
        float sc[8][4];
#pragma unroll
        for (int i = 0; i < 8; i++)
#pragma unroll
            for (int j = 0; j < 4; j++) sc[i][j] = 0.0f;
#pragma unroll
        for (int kk = 0; kk < 4; kk++) {
            const uint32_t offA = (uint32_t)(((kk * 2 + (lane >> 4)) ^ l7) << 4);
            const uint32_t offB = (uint32_t)(((kk * 2 + ((lane >> 3) & 1)) ^ l7) << 4);
            uint32_t ah[4];
            LDSM_X4(ah, s0 + aQ + offA);
#pragma unroll
            for (int nt2 = 0; nt2 < 4; nt2++) {
                uint32_t bh4[4];
                LDSM_X4(bh4, sK + nt2 * 2048 + offB);
                MMA16816(sc[2 * nt2],     ah, bh4[0], bh4[1]);
                MMA16816(sc[2 * nt2 + 1], ah, bh4[2], bh4[3]);
            }
        }

        // ---- causal mask ----
        if (kt >= 2 * qt) {
            const int baser = qt * 128 + wm + (lane >> 2);
            const int baseg = kt * 64 + ((lane & 3) << 1);
#pragma unroll
            for (int nt = 0; nt < 8; nt++)
#pragma unroll
                for (int j = 0; j < 4; j++) {
                    const int row = baser + ((j >> 1) << 3);
                    const int g   = baseg + nt * 8 + (j & 1);
                    if (g > row) sc[nt][j] = NEG_BIG;
                }
        }

        // ---- online softmax (exp2 domain) ----
#pragma unroll
        for (int hh = 0; hh < 2; hh++) {
            float rm = NEG_BIG;
#pragma unroll
            for (int nt = 0; nt < 8; nt++)
                rm = fmaxf(rm, fmaxf(sc[nt][2 * hh], sc[nt][2 * hh + 1]));
            rm = fmaxf(rm, __shfl_xor_sync(0xffffffffu, rm, 1));
            rm = fmaxf(rm, __shfl_xor_sync(0xffffffffu, rm, 2));
            const float mnew = fmaxf(mrow[hh], rm);
            const float corr = fast_exp2(mrow[hh] - mnew);
            mrow[hh] = mnew;
            float rs = 0.0f;
#pragma unroll
            for (int nt = 0; nt < 8; nt++) {
                sc[nt][2 * hh]     = fast_exp2(sc[nt][2 * hh] - mnew);
                sc[nt][2 * hh + 1] = fast_exp2(sc[nt][2 * hh + 1] - mnew);
                rs += sc[nt][2 * hh] + sc[nt][2 * hh + 1];
            }
            rs += __shfl_xor_sync(0xffffffffu, rs, 1);
            rs += __shfl_xor_sync(0xffffffffu, rs, 2);
            lrow[hh] = lrow[hh] * corr + rs;
#pragma unroll
            for (int nt = 0; nt < 8; nt++) {
                o[nt][2 * hh]     *= corr;
                o[nt][2 * hh + 1] *= corr;
            }
        }

        // ---- O += P @ V (1-term: V via trans-ldmatrix) ----
#pragma unroll
        for (int t = 0; t < 4; t++) {
            const int vrow = t * 16 + vrowb;
            uint32_t ap[4];
            ap[0] = pack_h(sc[2 * t][0],     sc[2 * t][1]);
            ap[1] = pack_h(sc[2 * t][2],     sc[2 * t][3]);
            ap[2] = pack_h(sc[2 * t + 1][0], sc[2 * t + 1][1]);
            ap[3] = pack_h(sc[2 * t + 1][2], sc[2 * t + 1][3]);
#pragma unroll
            for (int nt2 = 0; nt2 < 4; nt2++) {
                const int col16 = nt2 * 2 + vsel;
                const uint32_t vaddr = (uint32_t)(vrow * 128)
                                     + (uint32_t)((col16 ^ (vrow & 7)) << 4);
                uint32_t bh4[4];
                LDSM_X4_T(bh4, sV + vaddr);
                MMA16816(o[2 * nt2],     ap, bh4[0], bh4[1]);
                MMA16816(o[2 * nt2 + 1], ap, bh4[2], bh4[3]);
            }
        }
    }

    // ---- epilogue: normalize, write ctx fp16 ----
    const float inv0 = 1.0f / lrow[0];
    const float inv1 = 1.0f / lrow[1];
    const int b = bh >> 4, h = bh & 15;
    const int r0 = qt * 128 + wm + (lane >> 2);
    const int c0 = h * 64 + ((lane & 3) << 1);
#pragma unroll
    for (int nt = 0; nt < 8; nt++) {
        const size_t p0 = (size_t)(b * 2048 + r0) * 1024 + c0 + nt * 8;
        *(uint32_t*)&g_ctxh[p0] = pack_h(o[nt][0] * inv0, o[nt][1] * inv0);
        const size_t p1 = (size_t)(b * 2048 + r0 + 8) * 1024 + c0 + nt * 8;
        *(uint32_t*)&g_ctxh[p1] = pack_h(o[nt][2] * inv1, o[nt][3] * inv1);
    }
}

// ---------------------------------------------------------------------------
// Launch.  Input order (metadata): x, Wk, Wq, Wv, Wo, bo
// ---------------------------------------------------------------------------
extern "C" void kernel_launch(void* const* d_in, const int* in_sizes, int n_in,
                              void* d_out, int out_size)
{
    const float* x  = (const float*)d_in[0];
    const float* Wk = (const float*)d_in[1];
    const float* Wq = (const float*)d_in[2];
    const float* Wv = (const float*)d_in[3];
    const float* Wo = (const float*)d_in[4];
    const float* bo = (const float*)d_in[5];
    float* out = (float*)d_out;

    static bool attr_done = false;
    if (!attr_done) {
        cudaFuncSetAttribute(gemm_kernel<0>,
                             cudaFuncAttributeMaxDynamicSharedMemorySize, GEMM_DYN_SMEM);
        cudaFuncSetAttribute(gemm_kernel<1>,
                             cudaFuncAttributeMaxDynamicSharedMemorySize, GEMM_DYN_SMEM);
        cudaFuncSetAttribute(flash_mma_kernel,
                             cudaFuncAttributeMaxDynamicSharedMemorySize, FLASH_SMEM);
        attr_done = true;
    }

    split_all_kernel<<<12288, 256>>>((const float4*)x, (const float4*)Wq,
                                     (const float4*)Wk, (const float4*)Wv,
                                     (const float4*)Wo);

    // QKV projection: M=8192, virtual N = [Wq | Wk | Wv] = 3072
    dim3 g1(MTOT / 128, 3072 / 128);     // 64 x 24, 128-thread CTAs
    gemm_kernel<0><<<g1, 128, GEMM_DYN_SMEM>>>(nullptr, nullptr);

    dim3 g2(S_ / 128, B_ * H_);          // 16 x 64
    flash_mma_kernel<<<g2, 256, FLASH_SMEM>>>();

    // Output projection: M=8192, N=1024 (+ bias)
    dim3 g3(MTOT / 128, 1024 / 128);     // 64 x 8
    gemm_kernel<1><<<g3, 128, GEMM_DYN_SMEM>>>(bo, out);
}

// round 16
// speedup vs baseline: 2.8590x; 1.0139x over previous
#include <cuda_runtime.h>
#include <cuda_fp16.h>
#include <stdint.h>
#include <string.h>

// Problem constants
#define B_ 4
#define S_ 2048
#define D_ 1024
#define H_ 16
#define HS_ 64
#define MTOT (B_ * S_)   // 8192

// ---------------------------------------------------------------------------
// fp16 scratch (static device arrays — no allocation allowed)
// Everything 1-term fp16: x, W*, q, k, v, ctx.
// ---------------------------------------------------------------------------
__device__ __half g_xh[(size_t)MTOT * D_];
__device__ __half g_wqh[(size_t)D_ * D_];
__device__ __half g_wkh[(size_t)D_ * D_];
__device__ __half g_wvh[(size_t)D_ * D_];
__device__ __half g_woh[(size_t)D_ * D_];
// q,k,v: [bh][s][hs] fp16 (q pre-scaled by 0.125*log2e)
__device__ __half g_qh[(size_t)64 * S_ * HS_];
__device__ __half g_kh[(size_t)64 * S_ * HS_];
__device__ __half g_vh[(size_t)64 * S_ * HS_];
__device__ __half g_ctxh[(size_t)MTOT * D_];

// ---------------------------------------------------------------------------
// PTX helpers (arch-portable: sm_80+, valid on compute_103)
// ---------------------------------------------------------------------------
__device__ __forceinline__ uint32_t smem_u32(const void* p) {
    uint32_t a;
    asm("{ .reg .u64 t; cvta.to.shared.u64 t, %1; cvt.u32.u64 %0, t; }"
        : "=r"(a) : "l"(p));
    return a;
}

__device__ __forceinline__ float fast_exp2(float x) {
    float y;
    asm("ex2.approx.ftz.f32 %0, %1;" : "=f"(y) : "f"(x));
    return y;
}

#define CP_ASYNC16(dst, src) \
    asm volatile("cp.async.cg.shared.global [%0], [%1], 16;" \
        :: "r"(dst), "l"(src))
#define CP_COMMIT() asm volatile("cp.async.commit_group;" ::: "memory")
#define CP_WAIT(n)  asm volatile("cp.async.wait_group %0;" :: "n"(n) : "memory")

#define LDSM_X4(R, ADDR) \
    asm volatile("ldmatrix.sync.aligned.m8n8.x4.shared.b16 {%0,%1,%2,%3}, [%4];" \
        : "=r"((R)[0]), "=r"((R)[1]), "=r"((R)[2]), "=r"((R)[3]) : "r"(ADDR))

#define LDSM_X4_T(R, ADDR) \
    asm volatile("ldmatrix.sync.aligned.m8n8.x4.trans.shared.b16 {%0,%1,%2,%3}, [%4];" \
        : "=r"((R)[0]), "=r"((R)[1]), "=r"((R)[2]), "=r"((R)[3]) : "r"(ADDR))

// fp16 inputs, fp32 accumulate
#define MMA16816(C, A, B0, B1) \
    asm volatile("mma.sync.aligned.m16n8k16.row.col.f32.f16.f16.f32 " \
        "{%0,%1,%2,%3}, {%4,%5,%6,%7}, {%8,%9}, {%0,%1,%2,%3};" \
        : "+f"((C)[0]), "+f"((C)[1]), "+f"((C)[2]), "+f"((C)[3]) \
        : "r"((A)[0]), "r"((A)[1]), "r"((A)[2]), "r"((A)[3]), \
          "r"((B0)), "r"((B1)))

__device__ __forceinline__ uint32_t pack_h(float a, float b) {
    __half2 h = __floats2half2_rn(a, b);
    uint32_t u; memcpy(&u, &h, 4);
    return u;
}

// Mask / init constant: dominates all real scores, fits fp16 range, exp2 -> 0.
#define NEG_BIG (-30000.0f)

// ---------------------------------------------------------------------------
// Combined split kernel: fp32 -> fp16 (all tensors 1-term).
// ---------------------------------------------------------------------------
__global__ __launch_bounds__(256, 4) void split_all_kernel(
    const float4* __restrict__ x,  const float4* __restrict__ Wq,
    const float4* __restrict__ Wk, const float4* __restrict__ Wv,
    const float4* __restrict__ Wo)
{
    const int bid = blockIdx.x;
    const float4* src;
    uint2* dh;
    int base;
    if (bid < 8192)      { src = x;  dh = (uint2*)g_xh;  base = bid; }
    else if (bid < 9216) { src = Wq; dh = (uint2*)g_wqh; base = bid - 8192; }
    else if (bid < 10240){ src = Wk; dh = (uint2*)g_wkh; base = bid - 9216; }
    else if (bid < 11264){ src = Wv; dh = (uint2*)g_wvh; base = bid - 10240; }
    else                 { src = Wo; dh = (uint2*)g_woh; base = bid - 11264; }
    const int i = base * 256 + threadIdx.x;
    float4 v = src[i];
    __half2 h01 = __floats2half2_rn(v.x, v.y);
    __half2 h23 = __floats2half2_rn(v.z, v.w);
    uint2 hv;
    memcpy(&hv.x, &h01, 4); memcpy(&hv.y, &h23, 4);
    dh[i] = hv;
}

// ---------------------------------------------------------------------------
// 1-term fp16 GEMM: C = Ah . Bh.  BK=64 (full 128B swizzled rows, no holes).
// MODE 0: A = x, B = Wq/Wk/Wv; epilogue -> q (scaled), k, v fp16.
// MODE 1: A = ctx, B = Wo; epilogue fp32 out + bias.
// 128 threads, 4 warps (2x2), warp tile 64x64, CTA 128x128,
// 16 stages of K=64, 3-stage cp.async pipeline, 2 CTAs/SM.
// Smem/stage: A 128x64 fp16 = 16KB + B 16KB = 32KB; x3 = 96KB (unchanged).
// MMAs per warp per barrier: 128 (2x R15) -> barrier overhead halved.
// ---------------------------------------------------------------------------
#define GTILE 16384u
#define GSTAGE 32768u
#define GEMM_DYN_SMEM (3 * 32768)

template<int MODE>
__global__ __launch_bounds__(128, 2) void gemm_kernel(
    const float* __restrict__ bo, float* __restrict__ outp)
{
    extern __shared__ char smem[];
    const int tid  = threadIdx.x;
    const int lane = tid & 31;
    const int wid  = tid >> 5;
    const int wm   = (wid & 1) * 64;
    const int wn   = (wid >> 1) * 64;
    const int m0   = blockIdx.x * 128;
    const int n0   = blockIdx.y * 128;

    const __half *Ah, *Bh;
    int nbase;
    if (MODE == 0) {
        Ah = g_xh;
        const int mat = n0 >> 10;
        Bh = (mat == 0) ? g_wqh : ((mat == 1) ? g_wkh : g_wvh);
        nbase = n0 & 1023;
    } else {
        Ah = g_ctxh;
        Bh = g_woh;
        nbase = n0;
    }

    // Loader: row = tid>>3 (+16 per chunk, 8 chunks per tile), col = tid&7.
    // All 128 threads load: 8 A-chunks + 8 B-chunks of 16B per stage.
    const int lrow = tid >> 3, lcol = tid & 7;
    const char* aB = (const char*)(Ah
                     + (size_t)(m0 + lrow) * 1024 + lcol * 8);
    const char* bB = (const char*)(Bh
                     + (size_t)(nbase + lrow) * 1024 + lcol * 8);
    const uint32_t da = (uint32_t)(lrow * 128) + (uint32_t)((lcol ^ (lrow & 7)) << 4);
    const uint32_t db = GTILE + da;
    const uint32_t s0 = smem_u32(smem);

    // prologue: stages 0, 1  (stage s covers k byte offset 128*s)
#pragma unroll
    for (int s = 0; s < 2; s++) {
        const uint32_t sb = s0 + (uint32_t)s * GSTAGE;
#pragma unroll
        for (int i = 0; i < 8; i++) {
            CP_ASYNC16(sb + da + i * 2048, aB + s * 128 + (size_t)i * 32768);
            CP_ASYNC16(sb + db + i * 2048, bB + s * 128 + (size_t)i * 32768);
        }
        CP_COMMIT();
    }

    float c[4][8][4];
#pragma unroll
    for (int i = 0; i < 4; i++)
#pragma unroll
        for (int j = 0; j < 8; j++)
#pragma unroll
            for (int q = 0; q < 4; q++) c[i][j][q] = 0.0f;

    const int l7 = lane & 7;
    const uint32_t arowoff = (uint32_t)((wm + (lane & 15)) * 128);
    const uint32_t browoff = (uint32_t)((wn + (lane & 7) + ((lane >> 4) & 1) * 8) * 128);

    int sb_idx = 0;
    for (int s = 0; s < 16; s++) {
        if (s == 15) { CP_WAIT(0); } else { CP_WAIT(1); }
        __syncthreads();
        if (s + 2 < 16) {
            const int nb = (sb_idx + 2 >= 3) ? sb_idx - 1 : sb_idx + 2;
            const uint32_t sb2 = s0 + (uint32_t)nb * GSTAGE;
#pragma unroll
            for (int i = 0; i < 8; i++) {
                CP_ASYNC16(sb2 + da + i * 2048, aB + (s + 2) * 128 + (size_t)i * 32768);
                CP_ASYNC16(sb2 + db + i * 2048, bB + (s + 2) * 128 + (size_t)i * 32768);
            }
            CP_COMMIT();
        }

        const uint32_t sb = s0 + (uint32_t)sb_idx * GSTAGE;
        const uint32_t sA = sb + arowoff;
        const uint32_t sB = sb + GTILE + browoff;
#pragma unroll
        for (int kk = 0; kk < 4; kk++) {
            const uint32_t offA = (uint32_t)(((kk * 2 + (lane >> 4)) ^ l7) << 4);
            const uint32_t offB = (uint32_t)(((kk * 2 + ((lane >> 3) & 1)) ^ l7) << 4);
            uint32_t bh4[4][4];
#pragma unroll
            for (int g = 0; g < 4; g++)
                LDSM_X4(bh4[g], sB + g * 2048 + offB);
#pragma unroll
            for (int mi = 0; mi < 4; mi++) {
                uint32_t ah[4];
                LDSM_X4(ah, sA + mi * 2048 + offA);
#pragma unroll
                for (int g = 0; g < 4; g++) {
                    MMA16816(c[mi][2 * g],     ah, bh4[g][0], bh4[g][1]);
                    MMA16816(c[mi][2 * g + 1], ah, bh4[g][2], bh4[g][3]);
                }
            }
        }
        sb_idx = (sb_idx + 1 >= 3) ? 0 : sb_idx + 1;
    }

    // ---- epilogue (coalesced) ----
    const int mrow = lane >> 2;
    const int ncol = (lane & 3) * 2;
#pragma unroll
    for (int mi = 0; mi < 4; mi++)
#pragma unroll
        for (int nj = 0; nj < 8; nj++) {
            const int col = n0 + wn + nj * 8 + ncol;
#pragma unroll
            for (int half = 0; half < 2; half++) {
                const int m = m0 + wm + mi * 16 + mrow + half * 8;
                const float v0 = c[mi][nj][half * 2 + 0];
                const float v1 = c[mi][nj][half * 2 + 1];
                if (MODE == 0) {
                    const int mat = col >> 10;
                    const int loc = col & 1023;
                    const int h = loc >> 6, hs = loc & 63;
                    const int b = m >> 11, si = m & 2047;
                    const size_t p0 = (((size_t)(b * 16 + h)) * 2048 + si) * 64 + hs;
                    // q scaled by 0.125 * log2(e) for exp2-domain softmax
                    const float sc = (mat == 0) ? 0.18033688f : 1.0f;
                    __half* dst = (mat == 0) ? g_qh : ((mat == 1) ? g_kh : g_vh);
                    *(uint32_t*)&dst[p0] = pack_h(v0 * sc, v1 * sc);
                } else {
                    *(float2*)&outp[(size_t)m * 1024 + col] =
                        make_float2(v0 + bo[col], v1 + bo[col + 1]);
                }
            }
        }
}

// ---------------------------------------------------------------------------
// Flash attention: QK 1-term fp16, PV 1-term fp16 (fp32 accum everywhere).
// Swizzled smem, cp.async K/V double buffer, V via ldmatrix.trans,
// exp2-domain softmax, heavy-CTAs-first. (unchanged from R15)
// Smem: Q 16K | 2 stages x (K 8K | V 8K) = 48KB total.
// ---------------------------------------------------------------------------
#define FTILE 8192u
#define FSTAGE 16384u
#define FLASH_SMEM (16384 + 2 * 16384)   // 49152

__global__ __launch_bounds__(256, 2) void flash_mma_kernel()
{
    extern __shared__ char fsm[];
    const uint32_t s0 = smem_u32(fsm);
    const uint32_t oKV = 16384u;

    const int tid = threadIdx.x, lane = tid & 31, wid = tid >> 5;
    const int qt = (int)gridDim.x - 1 - (int)blockIdx.x;   // heavy first
    const int bh = blockIdx.y;
    const int wm = wid * 16;
    const int l7 = lane & 7;

    // ---- issue Q via cp.async (128 x 64 fp16 = 16KB = 1024 chunks) ----
#pragma unroll
    for (int i = 0; i < 4; i++) {
        const int cc  = i * 256 + tid;
        const int row = cc >> 3, col = cc & 7;
        const __half* qsrc = g_qh
            + (size_t)bh * 131072 + (size_t)(qt * 128 + row) * 64 + col * 8;
        CP_ASYNC16(s0 + (uint32_t)row * 128u
                       + (uint32_t)((col ^ (row & 7)) << 4), qsrc);
    }
    CP_COMMIT();

    // ---- KV loader: 2 tiles (K, V), each [64 keys][64 hs] = 512 chunks ----
    const char* skv[4];
    uint32_t dkv[4];
#pragma unroll
    for (int i = 0; i < 4; i++) {
        const int tile = i >> 1;                 // 0=K, 1=V
        const int cc   = (i & 1) * 256 + tid;
        const int row  = cc >> 3, col = cc & 7;
        const __half* bp = ((tile == 0) ? g_kh : g_vh)
            + (size_t)bh * 131072 + (size_t)row * 64 + col * 8;
        skv[i] = (const char*)bp;
        dkv[i] = oKV + (uint32_t)tile * FTILE + (uint32_t)row * 128u
               + (uint32_t)((col ^ (row & 7)) << 4);
    }
#pragma unroll
    for (int i = 0; i < 4; i++) CP_ASYNC16(s0 + dkv[i], skv[i]);
    CP_COMMIT();

    float o[8][4];
#pragma unroll
    for (int i = 0; i < 8; i++)
#pragma unroll
        for (int j = 0; j < 4; j++) o[i][j] = 0.0f;
    float mrow[2] = {NEG_BIG, NEG_BIG}, lrow[2] = {0.0f, 0.0f};

    const uint32_t aQ  = (uint32_t)((wm + (lane & 15)) * 128);
    const uint32_t bKV = (uint32_t)(((lane & 7) + ((lane >> 4) & 1) * 8) * 128);
    const int vrowb = (lane & 7) + 8 * ((lane >> 3) & 1);
    const int vsel  = (lane >> 4) & 1;

    const int nkt = 2 * qt + 2;
    for (int kt = 0; kt < nkt; kt++) {
        CP_WAIT(0);
        __syncthreads();
        if (kt + 1 < nkt) {
            const uint32_t st2 = (uint32_t)((kt + 1) & 1) * FSTAGE;
#pragma unroll
            for (int i = 0; i < 4; i++)
                CP_ASYNC16(s0 + st2 + dkv[i], skv[i] + (size_t)(kt + 1) * 8192);
            CP_COMMIT();
        }

        const uint32_t ss = (uint32_t)(kt & 1) * FSTAGE;
        const uint32_t sK = s0 + ss + oKV + bKV;
        const uint32_t sV = s0 + ss + oKV + FTILE;

        // ---- S_log2 = Q @ K^T (1-term fp16) ----
        float sc[8][4];
#pragma unroll
        for (int i = 0; i < 8; i++)
#pragma unroll
            for (int j = 0; j < 4; j++) sc[i][j] = 0.0f;
#pragma unroll
        for (int kk = 0; kk < 4; kk++) {
            const uint32_t offA = (uint32_t)(((kk * 2 + (lane >> 4)) ^ l7) << 4);
            const uint32_t offB = (uint32_t)(((kk * 2 + ((lane >> 3) & 1)) ^ l7) << 4);
            uint32_t ah[4];
            LDSM_X4(ah, s0 + aQ + offA);
#pragma unroll
            for (int nt2 = 0; nt2 < 4; nt2++) {
                uint32_t bh4[4];
                LDSM_X4(bh4, sK + nt2 * 2048 + offB);
                MMA16816(sc[2 * nt2],     ah, bh4[0], bh4[1]);
                MMA16816(sc[2 * nt2 + 1], ah, bh4[2], bh4[3]);
            }
        }

        // ---- causal mask ----
        if (kt >= 2 * qt) {
            const int baser = qt * 128 + wm + (lane >> 2);
            const int baseg = kt * 64 + ((lane & 3) << 1);
#pragma unroll
            for (int nt = 0; nt < 8; nt++)
#pragma unroll
                for (int j = 0; j < 4; j++) {
                    const int row = baser + ((j >> 1) << 3);
                    const int g   = baseg + nt * 8 + (j & 1);
                    if (g > row) sc[nt][j] = NEG_BIG;
                }
        }

        // ---- online softmax (exp2 domain) ----
#pragma unroll
        for (int hh = 0; hh < 2; hh++) {
            float rm = NEG_BIG;
#pragma unroll
            for (int nt = 0; nt < 8; nt++)
                rm = fmaxf(rm, fmaxf(sc[nt][2 * hh], sc[nt][2 * hh + 1]));
            rm = fmaxf(rm, __shfl_xor_sync(0xffffffffu, rm, 1));
            rm = fmaxf(rm, __shfl_xor_sync(0xffffffffu, rm, 2));
            const float mnew = fmaxf(mrow[hh], rm);
            const float corr = fast_exp2(mrow[hh] - mnew);
            mrow[hh] = mnew;
            float rs = 0.0f;
#pragma unroll
            for (int nt = 0; nt < 8; nt++) {
                sc[nt][2 * hh]     = fast_exp2(sc[nt][2 * hh] - mnew);
                sc[nt][2 * hh + 1] = fast_exp2(sc[nt][2 * hh + 1] - mnew);
                rs += sc[nt][2 * hh] + sc[nt][2 * hh + 1];
            }
            rs += __shfl_xor_sync(0xffffffffu, rs, 1);
            rs += __shfl_xor_sync(0xffffffffu, rs, 2);
            lrow[hh] = lrow[hh] * corr + rs;
#pragma unroll
            for (int nt = 0; nt < 8; nt++) {
                o[nt][2 * hh]     *= corr;
                o[nt][2 * hh + 1] *= corr;
            }
        }

        // ---- O += P @ V (1-term: V via trans-ldmatrix) ----
#pragma unroll
        for (int t = 0; t < 4; t++) {
            const int vrow = t * 16 + vrowb;
            uint32_t ap[4];
            ap[0] = pack_h(sc[2 * t][0],     sc[2 * t][1]);
            ap[1] = pack_h(sc[2 * t][2],     sc[2 * t][3]);
            ap[2] = pack_h(sc[2 * t + 1][0], sc[2 * t + 1][1]);
            ap[3] = pack_h(sc[2 * t + 1][2], sc[2 * t + 1][3]);
#pragma unroll
            for (int nt2 = 0; nt2 < 4; nt2++) {
                const int col16 = nt2 * 2 + vsel;
                const uint32_t vaddr = (uint32_t)(vrow * 128)
                                     + (uint32_t)((col16 ^ (vrow & 7)) << 4);
                uint32_t bh4[4];
                LDSM_X4_T(bh4, sV + vaddr);
                MMA16816(o[2 * nt2],     ap, bh4[0], bh4[1]);
                MMA16816(o[2 * nt2 + 1], ap, bh4[2], bh4[3]);
            }
        }
    }

    // ---- epilogue: normalize, write ctx fp16 ----
    const float inv0 = 1.0f / lrow[0];
    const float inv1 = 1.0f / lrow[1];
    const int b = bh >> 4, h = bh & 15;
    const int r0 = qt * 128 + wm + (lane >> 2);
    const int c0 = h * 64 + ((lane & 3) << 1);
#pragma unroll
    for (int nt = 0; nt < 8; nt++) {
        const size_t p0 = (size_t)(b * 2048 + r0) * 1024 + c0 + nt * 8;
        *(uint32_t*)&g_ctxh[p0] = pack_h(o[nt][0] * inv0, o[nt][1] * inv0);
        const size_t p1 = (size_t)(b * 2048 + r0 + 8) * 1024 + c0 + nt * 8;
        *(uint32_t*)&g_ctxh[p1] = pack_h(o[nt][2] * inv1, o[nt][3] * inv1);
    }
}

// ---------------------------------------------------------------------------
// Launch.  Input order (metadata): x, Wk, Wq, Wv, Wo, bo
// ---------------------------------------------------------------------------
extern "C" void kernel_launch(void* const* d_in, const int* in_sizes, int n_in,
                              void* d_out, int out_size)
{
    const float* x  = (const float*)d_in[0];
    const float* Wk = (const float*)d_in[1];
    const float* Wq = (const float*)d_in[2];
    const float* Wv = (const float*)d_in[3];
    const float* Wo = (const float*)d_in[4];
    const float* bo = (const float*)d_in[5];
    float* out = (float*)d_out;

    static bool attr_done = false;
    if (!attr_done) {
        cudaFuncSetAttribute(gemm_kernel<0>,
                             cudaFuncAttributeMaxDynamicSharedMemorySize, GEMM_DYN_SMEM);
        cudaFuncSetAttribute(gemm_kernel<1>,
                             cudaFuncAttributeMaxDynamicSharedMemorySize, GEMM_DYN_SMEM);
        cudaFuncSetAttribute(flash_mma_kernel,
                             cudaFuncAttributeMaxDynamicSharedMemorySize, FLASH_SMEM);
        attr_done = true;
    }

    split_all_kernel<<<12288, 256>>>((const float4*)x, (const float4*)Wq,
                                     (const float4*)Wk, (const float4*)Wv,
                                     (const float4*)Wo);

    // QKV projection: M=8192, virtual N = [Wq | Wk | Wv] = 3072
    dim3 g1(MTOT / 128, 3072 / 128);     // 64 x 24, 128-thread CTAs
    gemm_kernel<0><<<g1, 128, GEMM_DYN_SMEM>>>(nullptr, nullptr);

    dim3 g2(S_ / 128, B_ * H_);          // 16 x 64
    flash_mma_kernel<<<g2, 256, FLASH_SMEM>>>();

    // Output projection: M=8192, N=1024 (+ bias)
    dim3 g3(MTOT / 128, 1024 / 128);     // 64 x 8
    gemm_kernel<1><<<g3, 128, GEMM_DYN_SMEM>>>(bo, out);
}

// round 17
// speedup vs baseline: 2.8774x; 1.0064x over previous
#include <cuda_runtime.h>
#include <cuda_fp16.h>
#include <stdint.h>
#include <string.h>

// Problem constants
#define B_ 4
#define S_ 2048
#define D_ 1024
#define H_ 16
#define HS_ 64
#define MTOT (B_ * S_)   // 8192

// ---------------------------------------------------------------------------
// fp16 scratch (static device arrays — no allocation allowed)
// Everything 1-term fp16: x, W*, q, k, v, ctx.
// ---------------------------------------------------------------------------
__device__ __half g_xh[(size_t)MTOT * D_];
__device__ __half g_wqh[(size_t)D_ * D_];
__device__ __half g_wkh[(size_t)D_ * D_];
__device__ __half g_wvh[(size_t)D_ * D_];
__device__ __half g_woh[(size_t)D_ * D_];
// q,k,v: [bh][s][hs] fp16 (q pre-scaled by 0.125*log2e)
__device__ __half g_qh[(size_t)64 * S_ * HS_];
__device__ __half g_kh[(size_t)64 * S_ * HS_];
__device__ __half g_vh[(size_t)64 * S_ * HS_];
__device__ __half g_ctxh[(size_t)MTOT * D_];

// ---------------------------------------------------------------------------
// PTX helpers (arch-portable: sm_80+, valid on compute_103)
// ---------------------------------------------------------------------------
__device__ __forceinline__ uint32_t smem_u32(const void* p) {
    uint32_t a;
    asm("{ .reg .u64 t; cvta.to.shared.u64 t, %1; cvt.u32.u64 %0, t; }"
        : "=r"(a) : "l"(p));
    return a;
}

__device__ __forceinline__ float fast_exp2(float x) {
    float y;
    asm("ex2.approx.ftz.f32 %0, %1;" : "=f"(y) : "f"(x));
    return y;
}

#define CP_ASYNC16(dst, src) \
    asm volatile("cp.async.cg.shared.global [%0], [%1], 16;" \
        :: "r"(dst), "l"(src))
#define CP_COMMIT() asm volatile("cp.async.commit_group;" ::: "memory")
#define CP_WAIT(n)  asm volatile("cp.async.wait_group %0;" :: "n"(n) : "memory")

#define LDSM_X4(R, ADDR) \
    asm volatile("ldmatrix.sync.aligned.m8n8.x4.shared.b16 {%0,%1,%2,%3}, [%4];" \
        : "=r"((R)[0]), "=r"((R)[1]), "=r"((R)[2]), "=r"((R)[3]) : "r"(ADDR))

#define LDSM_X4_T(R, ADDR) \
    asm volatile("ldmatrix.sync.aligned.m8n8.x4.trans.shared.b16 {%0,%1,%2,%3}, [%4];" \
        : "=r"((R)[0]), "=r"((R)[1]), "=r"((R)[2]), "=r"((R)[3]) : "r"(ADDR))

// fp16 inputs, fp32 accumulate
#define MMA16816(C, A, B0, B1) \
    asm volatile("mma.sync.aligned.m16n8k16.row.col.f32.f16.f16.f32 " \
        "{%0,%1,%2,%3}, {%4,%5,%6,%7}, {%8,%9}, {%0,%1,%2,%3};" \
        : "+f"((C)[0]), "+f"((C)[1]), "+f"((C)[2]), "+f"((C)[3]) \
        : "r"((A)[0]), "r"((A)[1]), "r"((A)[2]), "r"((A)[3]), \
          "r"((B0)), "r"((B1)))

__device__ __forceinline__ uint32_t pack_h(float a, float b) {
    __half2 h = __floats2half2_rn(a, b);
    uint32_t u; memcpy(&u, &h, 4);
    return u;
}

// Mask / init constant: dominates all real scores, fits fp16 range, exp2 -> 0.
#define NEG_BIG (-30000.0f)

// ---------------------------------------------------------------------------
// Combined split kernel: fp32 -> fp16 (all tensors 1-term).
// ---------------------------------------------------------------------------
__global__ __launch_bounds__(256, 4) void split_all_kernel(
    const float4* __restrict__ x,  const float4* __restrict__ Wq,
    const float4* __restrict__ Wk, const float4* __restrict__ Wv,
    const float4* __restrict__ Wo)
{
    const int bid = blockIdx.x;
    const float4* src;
    uint2* dh;
    int base;
    if (bid < 8192)      { src = x;  dh = (uint2*)g_xh;  base = bid; }
    else if (bid < 9216) { src = Wq; dh = (uint2*)g_wqh; base = bid - 8192; }
    else if (bid < 10240){ src = Wk; dh = (uint2*)g_wkh; base = bid - 9216; }
    else if (bid < 11264){ src = Wv; dh = (uint2*)g_wvh; base = bid - 10240; }
    else                 { src = Wo; dh = (uint2*)g_woh; base = bid - 11264; }
    const int i = base * 256 + threadIdx.x;
    float4 v = src[i];
    __half2 h01 = __floats2half2_rn(v.x, v.y);
    __half2 h23 = __floats2half2_rn(v.z, v.w);
    uint2 hv;
    memcpy(&hv.x, &h01, 4); memcpy(&hv.y, &h23, 4);
    dh[i] = hv;
}

// ---------------------------------------------------------------------------
// 1-term fp16 GEMM: C = Ah . Bh.  BK=64, fragment double-buffered inner loop:
// kk+1's ldmatrix issues precede kk's MMAs, hiding LDS latency entirely.
// 128 threads, 4 warps (2x2), warp tile 64x64, CTA 128x128,
// 16 K-stages, 3-stage cp.async pipeline, 2 CTAs/SM, 96KB smem.
// ---------------------------------------------------------------------------
#define GTILE 16384u
#define GSTAGE 32768u
#define GEMM_DYN_SMEM (3 * 32768)

template<int MODE>
__global__ __launch_bounds__(128, 2) void gemm_kernel(
    const float* __restrict__ bo, float* __restrict__ outp)
{
    extern __shared__ char smem[];
    const int tid  = threadIdx.x;
    const int lane = tid & 31;
    const int wid  = tid >> 5;
    const int wm   = (wid & 1) * 64;
    const int wn   = (wid >> 1) * 64;
    const int m0   = blockIdx.x * 128;
    const int n0   = blockIdx.y * 128;

    const __half *Ah, *Bh;
    int nbase;
    if (MODE == 0) {
        Ah = g_xh;
        const int mat = n0 >> 10;
        Bh = (mat == 0) ? g_wqh : ((mat == 1) ? g_wkh : g_wvh);
        nbase = n0 & 1023;
    } else {
        Ah = g_ctxh;
        Bh = g_woh;
        nbase = n0;
    }

    const int lrow = tid >> 3, lcol = tid & 7;
    const char* aB = (const char*)(Ah
                     + (size_t)(m0 + lrow) * 1024 + lcol * 8);
    const char* bB = (const char*)(Bh
                     + (size_t)(nbase + lrow) * 1024 + lcol * 8);
    const uint32_t da = (uint32_t)(lrow * 128) + (uint32_t)((lcol ^ (lrow & 7)) << 4);
    const uint32_t db = GTILE + da;
    const uint32_t s0 = smem_u32(smem);

    // prologue: stages 0, 1
#pragma unroll
    for (int s = 0; s < 2; s++) {
        const uint32_t sb = s0 + (uint32_t)s * GSTAGE;
#pragma unroll
        for (int i = 0; i < 8; i++) {
            CP_ASYNC16(sb + da + i * 2048, aB + s * 128 + (size_t)i * 32768);
            CP_ASYNC16(sb + db + i * 2048, bB + s * 128 + (size_t)i * 32768);
        }
        CP_COMMIT();
    }

    float c[4][8][4];
#pragma unroll
    for (int i = 0; i < 4; i++)
#pragma unroll
        for (int j = 0; j < 8; j++)
#pragma unroll
            for (int q = 0; q < 4; q++) c[i][j][q] = 0.0f;

    const int l7 = lane & 7;
    const uint32_t arowoff = (uint32_t)((wm + (lane & 15)) * 128);
    const uint32_t browoff = (uint32_t)((wn + (lane & 7) + ((lane >> 4) & 1) * 8) * 128);
    const int aky = lane >> 4;          // k-halfgroup select for A
    const int bky = (lane >> 3) & 1;    // k-halfgroup select for B

    int sb_idx = 0;
    for (int s = 0; s < 16; s++) {
        if (s == 15) { CP_WAIT(0); } else { CP_WAIT(1); }
        __syncthreads();
        if (s + 2 < 16) {
            const int nb = (sb_idx + 2 >= 3) ? sb_idx - 1 : sb_idx + 2;
            const uint32_t sb2 = s0 + (uint32_t)nb * GSTAGE;
#pragma unroll
            for (int i = 0; i < 8; i++) {
                CP_ASYNC16(sb2 + da + i * 2048, aB + (s + 2) * 128 + (size_t)i * 32768);
                CP_ASYNC16(sb2 + db + i * 2048, bB + (s + 2) * 128 + (size_t)i * 32768);
            }
            CP_COMMIT();
        }

        const uint32_t sb = s0 + (uint32_t)sb_idx * GSTAGE;
        const uint32_t sA = sb + arowoff;
        const uint32_t sB = sb + GTILE + browoff;

        // fragment double buffers
        uint32_t aF[2][4][4], bF[2][4][4];
        // preload kk = 0
        {
            const uint32_t offA = (uint32_t)(((aky) ^ l7) << 4);
            const uint32_t offB = (uint32_t)(((bky) ^ l7) << 4);
#pragma unroll
            for (int g = 0; g < 4; g++)
                LDSM_X4(bF[0][g], sB + g * 2048 + offB);
#pragma unroll
            for (int mi = 0; mi < 4; mi++)
                LDSM_X4(aF[0][mi], sA + mi * 2048 + offA);
        }
#pragma unroll
        for (int kk = 0; kk < 4; kk++) {
            const int cur = kk & 1, nxt = cur ^ 1;
            if (kk < 3) {
                const uint32_t offA = (uint32_t)((((kk + 1) * 2 + aky) ^ l7) << 4);
                const uint32_t offB = (uint32_t)((((kk + 1) * 2 + bky) ^ l7) << 4);
#pragma unroll
                for (int g = 0; g < 4; g++)
                    LDSM_X4(bF[nxt][g], sB + g * 2048 + offB);
#pragma unroll
                for (int mi = 0; mi < 4; mi++)
                    LDSM_X4(aF[nxt][mi], sA + mi * 2048 + offA);
            }
#pragma unroll
            for (int mi = 0; mi < 4; mi++)
#pragma unroll
                for (int g = 0; g < 4; g++) {
                    MMA16816(c[mi][2 * g],     aF[cur][mi], bF[cur][g][0], bF[cur][g][1]);
                    MMA16816(c[mi][2 * g + 1], aF[cur][mi], bF[cur][g][2], bF[cur][g][3]);
                }
        }
        sb_idx = (sb_idx + 1 >= 3) ? 0 : sb_idx + 1;
    }

    // ---- epilogue (coalesced) ----
    const int mrow = lane >> 2;
    const int ncol = (lane & 3) * 2;
#pragma unroll
    for (int mi = 0; mi < 4; mi++)
#pragma unroll
        for (int nj = 0; nj < 8; nj++) {
            const int col = n0 + wn + nj * 8 + ncol;
#pragma unroll
            for (int half = 0; half < 2; half++) {
                const int m = m0 + wm + mi * 16 + mrow + half * 8;
                const float v0 = c[mi][nj][half * 2 + 0];
                const float v1 = c[mi][nj][half * 2 + 1];
                if (MODE == 0) {
                    const int mat = col >> 10;
                    const int loc = col & 1023;
                    const int h = loc >> 6, hs = loc & 63;
                    const int b = m >> 11, si = m & 2047;
                    const size_t p0 = (((size_t)(b * 16 + h)) * 2048 + si) * 64 + hs;
                    // q scaled by 0.125 * log2(e) for exp2-domain softmax
                    const float sc = (mat == 0) ? 0.18033688f : 1.0f;
                    __half* dst = (mat == 0) ? g_qh : ((mat == 1) ? g_kh : g_vh);
                    *(uint32_t*)&dst[p0] = pack_h(v0 * sc, v1 * sc);
                } else {
                    *(float2*)&outp[(size_t)m * 1024 + col] =
                        make_float2(v0 + bo[col], v1 + bo[col + 1]);
                }
            }
        }
}

// ---------------------------------------------------------------------------
// Flash attention: QK 1-term fp16, PV 1-term fp16 (fp32 accum everywhere).
// Swizzled smem, cp.async K/V double buffer, V via ldmatrix.trans,
// exp2-domain softmax, heavy-CTAs-first. (unchanged from R15/R16)
// Smem: Q 16K | 2 stages x (K 8K | V 8K) = 48KB total.
// ---------------------------------------------------------------------------
#define FTILE 8192u
#define FSTAGE 16384u
#define FLASH_SMEM (16384 + 2 * 16384)   // 49152

__global__ __launch_bounds__(256, 2) void flash_mma_kernel()
{
    extern __shared__ char fsm[];
    const uint32_t s0 = smem_u32(fsm);
    const uint32_t oKV = 16384u;

    const int tid = threadIdx.x, lane = tid & 31, wid = tid >> 5;
    const int qt = (int)gridDim.x - 1 - (int)blockIdx.x;   // heavy first
    const int bh = blockIdx.y;
    const int wm = wid * 16;
    const int l7 = lane & 7;

    // ---- issue Q via cp.async ----
#pragma unroll
    for (int i = 0; i < 4; i++) {
        const int cc  = i * 256 + tid;
        const int row = cc >> 3, col = cc & 7;
        const __half* qsrc = g_qh
            + (size_t)bh * 131072 + (size_t)(qt * 128 + row) * 64 + col * 8;
        CP_ASYNC16(s0 + (uint32_t)row * 128u
                       + (uint32_t)((col ^ (row & 7)) << 4), qsrc);
    }
    CP_COMMIT();

    // ---- KV loader: 2 tiles (K, V), each [64 keys][64 hs] ----
    const char* skv[4];
    uint32_t dkv[4];
#pragma unroll
    for (int i = 0; i < 4; i++) {
        const int tile = i >> 1;
        const int cc   = (i & 1) * 256 + tid;
        const int row  = cc >> 3, col = cc & 7;
        const __half* bp = ((tile == 0) ? g_kh : g_vh)
            + (size_t)bh * 131072 + (size_t)row * 64 + col * 8;
        skv[i] = (const char*)bp;
        dkv[i] = oKV + (uint32_t)tile * FTILE + (uint32_t)row * 128u
               + (uint32_t)((col ^ (row & 7)) << 4);
    }
#pragma unroll
    for (int i = 0; i < 4; i++) CP_ASYNC16(s0 + dkv[i], skv[i]);
    CP_COMMIT();

    float o[8][4];
#pragma unroll
    for (int i = 0; i < 8; i++)
#pragma unroll
        for (int j = 0; j < 4; j++) o[i][j] = 0.0f;
    float mrow[2] = {NEG_BIG, NEG_BIG}, lrow[2] = {0.0f, 0.0f};

    const uint32_t aQ  = (uint32_t)((wm + (lane & 15)) * 128);
    const uint32_t bKV = (uint32_t)(((lane & 7) + ((lane >> 4) & 1) * 8) * 128);
    const int vrowb = (lane & 7) + 8 * ((lane >> 3) & 1);
    const int vsel  = (lane >> 4) & 1;

    const int nkt = 2 * qt + 2;
    for (int kt = 0; kt < nkt; kt++) {
        CP_WAIT(0);
        __syncthreads();
        if (kt + 1 < nkt) {
            const uint32_t st2 = (uint32_t)((kt + 1) & 1) * FSTAGE;
#pragma unroll
            for (int i = 0; i < 4; i++)
                CP_ASYNC16(s0 + st2 + dkv[i], skv[i] + (size_t)(kt + 1) * 8192);
            CP_COMMIT();
        }

        const uint32_t ss = (uint32_t)(kt & 1) * FSTAGE;
        const uint32_t sK = s0 + ss + oKV + bKV;
        const uint32_t sV = s0 + ss + oKV + FTILE;

        // ---- S_log2 = Q @ K^T (1-term fp16) ----
        float sc[8][4];
#pragma unroll
        for (int i = 0; i < 8; i++)
#pragma unroll
            for (int j = 0; j < 4; j++) sc[i][j] = 0.0f;
#pragma unroll
        for (int kk = 0; kk < 4; kk++) {
            const uint32_t offA = (uint32_t)(((kk * 2 + (lane >> 4)) ^ l7) << 4);
            const uint32_t offB = (uint32_t)(((kk * 2 + ((lane >> 3) & 1)) ^ l7) << 4);
            uint32_t ah[4];
            LDSM_X4(ah, s0 + aQ + offA);
#pragma unroll
            for (int nt2 = 0; nt2 < 4; nt2++) {
                uint32_t bh4[4];
                LDSM_X4(bh4, sK + nt2 * 2048 + offB);
                MMA16816(sc[2 * nt2],     ah, bh4[0], bh4[1]);
                MMA16816(sc[2 * nt2 + 1], ah, bh4[2], bh4[3]);
            }
        }

        // ---- causal mask ----
        if (kt >= 2 * qt) {
            const int baser = qt * 128 + wm + (lane >> 2);
            const int baseg = kt * 64 + ((lane & 3) << 1);
#pragma unroll
            for (int nt = 0; nt < 8; nt++)
#pragma unroll
                for (int j = 0; j < 4; j++) {
                    const int row = baser + ((j >> 1) << 3);
                    const int g   = baseg + nt * 8 + (j & 1);
                    if (g > row) sc[nt][j] = NEG_BIG;
                }
        }

        // ---- online softmax (exp2 domain) ----
#pragma unroll
        for (int hh = 0; hh < 2; hh++) {
            float rm = NEG_BIG;
#pragma unroll
            for (int nt = 0; nt < 8; nt++)
                rm = fmaxf(rm, fmaxf(sc[nt][2 * hh], sc[nt][2 * hh + 1]));
            rm = fmaxf(rm, __shfl_xor_sync(0xffffffffu, rm, 1));
            rm = fmaxf(rm, __shfl_xor_sync(0xffffffffu, rm, 2));
            const float mnew = fmaxf(mrow[hh], rm);
            const float corr = fast_exp2(mrow[hh] - mnew);
            mrow[hh] = mnew;
            float rs = 0.0f;
#pragma unroll
            for (int nt = 0; nt < 8; nt++) {
                sc[nt][2 * hh]     = fast_exp2(sc[nt][2 * hh] - mnew);
                sc[nt][2 * hh + 1] = fast_exp2(sc[nt][2 * hh + 1] - mnew);
                rs += sc[nt][2 * hh] + sc[nt][2 * hh + 1];
            }
            rs += __shfl_xor_sync(0xffffffffu, rs, 1);
            rs += __shfl_xor_sync(0xffffffffu, rs, 2);
            lrow[hh] = lrow[hh] * corr + rs;
#pragma unroll
            for (int nt = 0; nt < 8; nt++) {
                o[nt][2 * hh]     *= corr;
                o[nt][2 * hh + 1] *= corr;
            }
        }

        // ---- O += P @ V (1-term: V via trans-ldmatrix) ----
#pragma unroll
        for (int t = 0; t < 4; t++) {
            const int vrow = t * 16 + vrowb;
            uint32_t ap[4];
            ap[0] = pack_h(sc[2 * t][0],     sc[2 * t][1]);
            ap[1] = pack_h(sc[2 * t][2],     sc[2 * t][3]);
            ap[2] = pack_h(sc[2 * t + 1][0], sc[2 * t + 1][1]);
            ap[3] = pack_h(sc[2 * t + 1][2], sc[2 * t + 1][3]);
#pragma unroll
            for (int nt2 = 0; nt2 < 4; nt2++) {
                const int col16 = nt2 * 2 + vsel;
                const uint32_t vaddr = (uint32_t)(vrow * 128)
                                     + (uint32_t)((col16 ^ (vrow & 7)) << 4);
                uint32_t bh4[4];
                LDSM_X4_T(bh4, sV + vaddr);
                MMA16816(o[2 * nt2],     ap, bh4[0], bh4[1]);
                MMA16816(o[2 * nt2 + 1], ap, bh4[2], bh4[3]);
            }
        }
    }

    // ---- epilogue: normalize, write ctx fp16 ----
    const float inv0 = 1.0f / lrow[0];
    const float inv1 = 1.0f / lrow[1];
    const int b = bh >> 4, h = bh & 15;
    const int r0 = qt * 128 + wm + (lane >> 2);
    const int c0 = h * 64 + ((lane & 3) << 1);
#pragma unroll
    for (int nt = 0; nt < 8; nt++) {
        const size_t p0 = (size_t)(b * 2048 + r0) * 1024 + c0 + nt * 8;
        *(uint32_t*)&g_ctxh[p0] = pack_h(o[nt][0] * inv0, o[nt][1] * inv0);
        const size_t p1 = (size_t)(b * 2048 + r0 + 8) * 1024 + c0 + nt * 8;
        *(uint32_t*)&g_ctxh[p1] = pack_h(o[nt][2] * inv1, o[nt][3] * inv1);
    }
}

// ---------------------------------------------------------------------------
// Launch.  Input order (metadata): x, Wk, Wq, Wv, Wo, bo
// ---------------------------------------------------------------------------
extern "C" void kernel_launch(void* const* d_in, const int* in_sizes, int n_in,
                              void* d_out, int out_size)
{
    const float* x  = (const float*)d_in[0];
    const float* Wk = (const float*)d_in[1];
    const float* Wq = (const float*)d_in[2];
    const float* Wv = (const float*)d_in[3];
    const float* Wo = (const float*)d_in[4];
    const float* bo = (const float*)d_in[5];
    float* out = (float*)d_out;

    static bool attr_done = false;
    if (!attr_done) {
        cudaFuncSetAttribute(gemm_kernel<0>,
                             cudaFuncAttributeMaxDynamicSharedMemorySize, GEMM_DYN_SMEM);
        cudaFuncSetAttribute(gemm_kernel<1>,
                             cudaFuncAttributeMaxDynamicSharedMemorySize, GEMM_DYN_SMEM);
        cudaFuncSetAttribute(flash_mma_kernel,
                             cudaFuncAttributeMaxDynamicSharedMemorySize, FLASH_SMEM);
        attr_done = true;
    }

    split_all_kernel<<<12288, 256>>>((const float4*)x, (const float4*)Wq,
                                     (const float4*)Wk, (const float4*)Wv,
                                     (const float4*)Wo);

    // QKV projection: M=8192, virtual N = [Wq | Wk | Wv] = 3072
    dim3 g1(MTOT / 128, 3072 / 128);     // 64 x 24, 128-thread CTAs
    gemm_kernel<0><<<g1, 128, GEMM_DYN_SMEM>>>(nullptr, nullptr);

    dim3 g2(S_ / 128, B_ * H_);          // 16 x 64
    flash_mma_kernel<<<g2, 256, FLASH_SMEM>>>();

    // Output projection: M=8192, N=1024 (+ bias)
    dim3 g3(MTOT / 128, 1024 / 128);     // 64 x 8
    gemm_kernel<1><<<g3, 128, GEMM_DYN_SMEM>>>(bo, out);
}